// round 1
// baseline (speedup 1.0000x reference)
#include <cuda_runtime.h>
#include <math.h>

#define B_   4
#define S_   4096
#define E_   2048
#define M_   2048
#define N1   (B_ * S_)            // 16384 rows
#define DECAY_F 0.95f
#define SCALE_F 0.22360679774997896f  // sqrt(1 - 0.95)

#define TS   256                  // seq tile for the scan
#define NT   (S_ / TS)            // 16 tiles per sequence

// Scratch (device globals: allocation-free per harness rules)
__device__ float g_store[(size_t)N1 * M_];   // (x@Wv)*sigmoid(x@Wg+bg)*scale
__device__ float g_que  [(size_t)N1 * M_];   // sigmoid(x@Wq+bq)*scale
__device__ float g_load [(size_t)N1 * M_];   // mem * que
__device__ float g_carry [B_ * NT * M_];
__device__ float g_prefix[B_ * NT * M_];

__device__ __forceinline__ float sigmoidf_(float v) {
    return 1.0f / (1.0f + expf(-v));
}

// ---------------------------------------------------------------------------
// Kernel 1: fused triple GEMM.  C_* = x @ W_* for Wv, Wg, Wq on the same
// 128x64 output tile; x tile is loaded once from SMEM for all three.
// Epilogue fuses the sigmoid gating and scaling.
// Block: 256 threads, tile 128(M rows) x 64(N cols), BK=16, 8x4 per thread
// per matrix (96 fp32 accumulators).
// ---------------------------------------------------------------------------
__global__ __launch_bounds__(256) void gemm3_kernel(
    const float* __restrict__ x,
    const float* __restrict__ Wv,
    const float* __restrict__ Wg,
    const float* __restrict__ Wq,
    const float* __restrict__ bg,
    const float* __restrict__ bq)
{
    const int BK = 16;
    __shared__ float As[16][128];
    __shared__ float Bv[16][64];
    __shared__ float Bg[16][64];
    __shared__ float Bq[16][64];

    const int tid = threadIdx.x;
    const int bn  = blockIdx.x * 64;    // m offset
    const int bm  = blockIdx.y * 128;   // row (b*S+s) offset
    const int tx  = tid & 15;           // col group 0..15  (4 cols each)
    const int ty  = tid >> 4;           // row group 0..15  (8 rows each)

    float accv[8][4], accg[8][4], accq[8][4];
    #pragma unroll
    for (int i = 0; i < 8; i++)
        #pragma unroll
        for (int j = 0; j < 4; j++) { accv[i][j] = 0.f; accg[i][j] = 0.f; accq[i][j] = 0.f; }

    for (int k0 = 0; k0 < E_; k0 += BK) {
        // Load A tile (128x16) transposed into SMEM, 2 float4 per thread
        #pragma unroll
        for (int i = 0; i < 2; i++) {
            int f   = tid + i * 256;            // 0..511 float4 slots
            int row = f >> 2;
            int kq  = (f & 3) * 4;
            float4 v = *reinterpret_cast<const float4*>(
                &x[(size_t)(bm + row) * E_ + k0 + kq]);
            As[kq + 0][row] = v.x;
            As[kq + 1][row] = v.y;
            As[kq + 2][row] = v.z;
            As[kq + 3][row] = v.w;
        }
        // Load the three 16x64 weight tiles, 1 float4 per thread per matrix
        {
            int k = tid >> 4;
            int c = (tid & 15) * 4;
            size_t off = (size_t)(k0 + k) * M_ + bn + c;
            *reinterpret_cast<float4*>(&Bv[k][c]) = *reinterpret_cast<const float4*>(&Wv[off]);
            *reinterpret_cast<float4*>(&Bg[k][c]) = *reinterpret_cast<const float4*>(&Wg[off]);
            *reinterpret_cast<float4*>(&Bq[k][c]) = *reinterpret_cast<const float4*>(&Wq[off]);
        }
        __syncthreads();

        #pragma unroll
        for (int k = 0; k < BK; k++) {
            float av[8];
            float4 a0 = *reinterpret_cast<const float4*>(&As[k][ty * 8 + 0]);
            float4 a1 = *reinterpret_cast<const float4*>(&As[k][ty * 8 + 4]);
            av[0]=a0.x; av[1]=a0.y; av[2]=a0.z; av[3]=a0.w;
            av[4]=a1.x; av[5]=a1.y; av[6]=a1.z; av[7]=a1.w;
            float4 v4 = *reinterpret_cast<const float4*>(&Bv[k][tx * 4]);
            float4 g4 = *reinterpret_cast<const float4*>(&Bg[k][tx * 4]);
            float4 q4 = *reinterpret_cast<const float4*>(&Bq[k][tx * 4]);
            float bvv[4] = {v4.x, v4.y, v4.z, v4.w};
            float bgg[4] = {g4.x, g4.y, g4.z, g4.w};
            float bqq[4] = {q4.x, q4.y, q4.z, q4.w};
            #pragma unroll
            for (int i = 0; i < 8; i++) {
                #pragma unroll
                for (int j = 0; j < 4; j++) {
                    accv[i][j] = fmaf(av[i], bvv[j], accv[i][j]);
                    accg[i][j] = fmaf(av[i], bgg[j], accg[i][j]);
                    accq[i][j] = fmaf(av[i], bqq[j], accq[i][j]);
                }
            }
        }
        __syncthreads();
    }

    // Epilogue: gated store + scaled query gate
    #pragma unroll
    for (int i = 0; i < 8; i++) {
        size_t rowoff = (size_t)(bm + ty * 8 + i) * M_;
        #pragma unroll
        for (int j = 0; j < 4; j++) {
            int m = bn + tx * 4 + j;
            float gate = sigmoidf_(accg[i][j] + bg[m]);
            g_store[rowoff + m] = accv[i][j] * gate * SCALE_F;
            g_que[rowoff + m]   = sigmoidf_(accq[i][j] + bq[m]) * SCALE_F;
        }
    }
}

// ---------------------------------------------------------------------------
// Kernel 2: local scan carries.  Each thread owns one m-column within a
// (b, seq-tile) and computes the tile-local inclusive-scan final value
// starting from 0.  Loads coalesce across m.
// ---------------------------------------------------------------------------
__global__ __launch_bounds__(128) void carry_kernel()
{
    int m = blockIdx.x * 128 + threadIdx.x;
    int j = blockIdx.y;
    int b = blockIdx.z;
    size_t base = ((size_t)(b * S_ + j * TS)) * M_ + m;
    float c = 0.f;
    #pragma unroll 8
    for (int t = 0; t < TS; t++)
        c = fmaf(DECAY_F, c, g_store[base + (size_t)t * M_]);
    g_carry[(size_t)(b * NT + j) * M_ + m] = c;
}

// ---------------------------------------------------------------------------
// Kernel 3: scan the 16 tile carries per (b, m) column.
// prefix[j] = mem value at the end of tile j-1 (incoming state for tile j).
// ---------------------------------------------------------------------------
__global__ __launch_bounds__(256) void prefix_kernel()
{
    int gid = blockIdx.x * blockDim.x + threadIdx.x;  // over B_*M_
    int b = gid / M_;
    int m = gid % M_;
    float aTS = DECAY_F;
    #pragma unroll
    for (int i = 0; i < 8; i++) aTS *= aTS;           // 0.95^256
    float run = 0.f;
    #pragma unroll
    for (int j = 0; j < NT; j++) {
        size_t idx = (size_t)(b * NT + j) * M_ + m;
        g_prefix[idx] = run;
        run = g_carry[idx] + aTS * run;
    }
}

// ---------------------------------------------------------------------------
// Kernel 4: re-run the local recurrence seeded with the incoming prefix,
// multiply by the (pre-scaled) query gate, write g_load.
// ---------------------------------------------------------------------------
__global__ __launch_bounds__(128) void apply_kernel()
{
    int m = blockIdx.x * 128 + threadIdx.x;
    int j = blockIdx.y;
    int b = blockIdx.z;
    size_t base = ((size_t)(b * S_ + j * TS)) * M_ + m;
    float c = g_prefix[(size_t)(b * NT + j) * M_ + m];
    #pragma unroll 4
    for (int t = 0; t < TS; t++) {
        size_t idx = base + (size_t)t * M_;
        c = fmaf(DECAY_F, c, g_store[idx]);
        g_load[idx] = c * g_que[idx];
    }
}

// ---------------------------------------------------------------------------
// Kernel 5: output GEMM  out = g_load @ Wo   (16384 x 2048 x 2048)
// 128x128 tile, BK=16, 8x8 per thread, 256 threads.
// ---------------------------------------------------------------------------
__global__ __launch_bounds__(256) void gemm_out_kernel(
    const float* __restrict__ Wo, float* __restrict__ out)
{
    const int BK = 16;
    __shared__ float As[16][128];
    __shared__ float Bs[16][128];

    const int tid = threadIdx.x;
    const int bn  = blockIdx.x * 128;   // e offset
    const int bm  = blockIdx.y * 128;   // row offset
    const int tx  = tid & 15;
    const int ty  = tid >> 4;

    float acc[8][8];
    #pragma unroll
    for (int i = 0; i < 8; i++)
        #pragma unroll
        for (int j = 0; j < 8; j++) acc[i][j] = 0.f;

    for (int k0 = 0; k0 < M_; k0 += BK) {
        #pragma unroll
        for (int i = 0; i < 2; i++) {
            int f   = tid + i * 256;
            int row = f >> 2;
            int kq  = (f & 3) * 4;
            float4 v = *reinterpret_cast<const float4*>(
                &g_load[(size_t)(bm + row) * M_ + k0 + kq]);
            As[kq + 0][row] = v.x;
            As[kq + 1][row] = v.y;
            As[kq + 2][row] = v.z;
            As[kq + 3][row] = v.w;
        }
        #pragma unroll
        for (int i = 0; i < 2; i++) {
            int f = tid + i * 256;            // 512 float4 of B tile (16x128)
            int k = f >> 5;
            int c = (f & 31) * 4;
            *reinterpret_cast<float4*>(&Bs[k][c]) =
                *reinterpret_cast<const float4*>(&Wo[(size_t)(k0 + k) * E_ + bn + c]);
        }
        __syncthreads();

        #pragma unroll
        for (int k = 0; k < BK; k++) {
            float ar[8], br[8];
            float4 a0 = *reinterpret_cast<const float4*>(&As[k][ty * 8 + 0]);
            float4 a1 = *reinterpret_cast<const float4*>(&As[k][ty * 8 + 4]);
            ar[0]=a0.x; ar[1]=a0.y; ar[2]=a0.z; ar[3]=a0.w;
            ar[4]=a1.x; ar[5]=a1.y; ar[6]=a1.z; ar[7]=a1.w;
            float4 b0 = *reinterpret_cast<const float4*>(&Bs[k][tx * 8 + 0]);
            float4 b1 = *reinterpret_cast<const float4*>(&Bs[k][tx * 8 + 4]);
            br[0]=b0.x; br[1]=b0.y; br[2]=b0.z; br[3]=b0.w;
            br[4]=b1.x; br[5]=b1.y; br[6]=b1.z; br[7]=b1.w;
            #pragma unroll
            for (int i = 0; i < 8; i++)
                #pragma unroll
                for (int j = 0; j < 8; j++)
                    acc[i][j] = fmaf(ar[i], br[j], acc[i][j]);
        }
        __syncthreads();
    }

    #pragma unroll
    for (int i = 0; i < 8; i++) {
        size_t ro = (size_t)(bm + ty * 8 + i) * E_;
        #pragma unroll
        for (int j = 0; j < 8; j += 4) {
            float4 v = make_float4(acc[i][j], acc[i][j+1], acc[i][j+2], acc[i][j+3]);
            *reinterpret_cast<float4*>(&out[ro + bn + tx * 8 + j]) = v;
        }
    }
}

// ---------------------------------------------------------------------------
extern "C" void kernel_launch(void* const* d_in, const int* in_sizes, int n_in,
                              void* d_out, int out_size)
{
    const float* x  = (const float*)d_in[0];
    const float* Wv = (const float*)d_in[1];
    const float* Wg = (const float*)d_in[2];
    const float* bg = (const float*)d_in[3];
    const float* Wq = (const float*)d_in[4];
    const float* bq = (const float*)d_in[5];
    const float* Wo = (const float*)d_in[6];
    float* out = (float*)d_out;

    dim3 g1(M_ / 64, N1 / 128);
    gemm3_kernel<<<g1, 256>>>(x, Wv, Wg, Wq, bg, bq);

    dim3 gscan(M_ / 128, NT, B_);
    carry_kernel<<<gscan, 128>>>();
    prefix_kernel<<<(B_ * M_) / 256, 256>>>();
    apply_kernel<<<gscan, 128>>>();

    dim3 g3(E_ / 128, N1 / 128);
    gemm_out_kernel<<<g3, 256>>>(Wo, out);
}

// round 3
// speedup vs baseline: 2.3238x; 2.3238x over previous
#include <cuda_runtime.h>
#include <cuda_bf16.h>
#include <cstdint>
#include <math.h>

#define B_   4
#define S_   4096
#define E_   2048
#define M_   2048
#define N1   (B_ * S_)
#define DECAY_F 0.95f
#define SCALE_F 0.22360679774997896f
#define TS   256
#define NT   (S_ / TS)

// ---------------- device scratch ----------------
__device__ float g_store[(size_t)N1 * M_];
__device__ float g_que  [(size_t)N1 * M_];
__device__ float g_carry [B_ * NT * M_];
__device__ float g_prefix[B_ * NT * M_];
__device__ __nv_bfloat16 g_xh[(size_t)N1 * E_], g_xl[(size_t)N1 * E_];
__device__ __nv_bfloat16 g_ldh[(size_t)N1 * M_], g_ldl[(size_t)N1 * M_];
__device__ __nv_bfloat16 g_wvh[(size_t)E_ * M_], g_wvl[(size_t)E_ * M_];
__device__ __nv_bfloat16 g_wgh[(size_t)E_ * M_], g_wgl[(size_t)E_ * M_];
__device__ __nv_bfloat16 g_wqh[(size_t)E_ * M_], g_wql[(size_t)E_ * M_];
__device__ __nv_bfloat16 g_woh[(size_t)E_ * M_], g_wol[(size_t)E_ * M_];

// ---------------- helpers ----------------
__device__ __forceinline__ uint32_t smem_u32(const void* p) {
    uint32_t a;
    asm("{ .reg .u64 t; cvta.to.shared.u64 t, %1; cvt.u32.u64 %0, t; }" : "=r"(a) : "l"(p));
    return a;
}
#define CP16(dst, src) \
    asm volatile("cp.async.cg.shared.global [%0], [%1], 16;" :: "r"(dst), "l"(src))
#define CP_COMMIT() asm volatile("cp.async.commit_group;" ::: "memory")
#define CP_WAIT(n)  asm volatile("cp.async.wait_group %0;" :: "n"(n) : "memory")

__device__ __forceinline__ uint32_t lds32(uint32_t addr) {
    uint32_t v;
    asm volatile("ld.shared.b32 %0, [%1];" : "=r"(v) : "r"(addr));
    return v;
}
__device__ __forceinline__ void mma16816(float* d, const uint32_t* a, const uint32_t* b) {
    asm volatile(
        "mma.sync.aligned.m16n8k16.row.col.f32.bf16.bf16.f32 "
        "{%0,%1,%2,%3}, {%4,%5,%6,%7}, {%8,%9}, {%0,%1,%2,%3};"
        : "+f"(d[0]), "+f"(d[1]), "+f"(d[2]), "+f"(d[3])
        : "r"(a[0]), "r"(a[1]), "r"(a[2]), "r"(a[3]), "r"(b[0]), "r"(b[1]));
}
__device__ __forceinline__ float sigf(float v) { return 1.0f / (1.0f + __expf(-v)); }

#define PADB 80   // 64B of bf16 data + 16B pad per row => conflict-free frag loads

// ---------------- conversion kernels ----------------
__global__ __launch_bounds__(256) void split_x_kernel(const float* __restrict__ x) {
    size_t i = (size_t)blockIdx.x * 256 + threadIdx.x;
    float4 v = reinterpret_cast<const float4*>(x)[i];
    __nv_bfloat16 h0 = __float2bfloat16(v.x), h1 = __float2bfloat16(v.y);
    __nv_bfloat16 h2 = __float2bfloat16(v.z), h3 = __float2bfloat16(v.w);
    reinterpret_cast<__nv_bfloat162*>(g_xh)[2*i]   = __nv_bfloat162(h0, h1);
    reinterpret_cast<__nv_bfloat162*>(g_xh)[2*i+1] = __nv_bfloat162(h2, h3);
    reinterpret_cast<__nv_bfloat162*>(g_xl)[2*i] =
        __nv_bfloat162(__float2bfloat16(v.x - __bfloat162float(h0)),
                       __float2bfloat16(v.y - __bfloat162float(h1)));
    reinterpret_cast<__nv_bfloat162*>(g_xl)[2*i+1] =
        __nv_bfloat162(__float2bfloat16(v.z - __bfloat162float(h2)),
                       __float2bfloat16(v.w - __bfloat162float(h3)));
}

// W[k][n] -> Th/Tl[n][k]
__global__ __launch_bounds__(256) void tsplit_kernel(const float* __restrict__ W,
                                                     __nv_bfloat16* __restrict__ Th,
                                                     __nv_bfloat16* __restrict__ Tl) {
    __shared__ float tile[32][33];
    int bx = blockIdx.x * 32, by = blockIdx.y * 32;
    int tx = threadIdx.x & 31, ty = threadIdx.x >> 5;
    #pragma unroll
    for (int i = ty; i < 32; i += 8)
        tile[i][tx] = W[(size_t)(by + i) * M_ + bx + tx];
    __syncthreads();
    #pragma unroll
    for (int i = ty; i < 32; i += 8) {
        float v = tile[tx][i];
        __nv_bfloat16 h = __float2bfloat16(v);
        size_t o = (size_t)(bx + i) * E_ + by + tx;
        Th[o] = h;
        Tl[o] = __float2bfloat16(v - __bfloat162float(h));
    }
}

// ---------------- gemm3: 128x(3x64) tile, mma.sync bf16, 3-pass split ----------------
#define ST3 (2*128*PADB + 6*64*PADB)   // 51200 bytes/stage
#define NKT3 (E_ / 32)                  // 64
__global__ __launch_bounds__(256, 1) void gemm3_mma(const float* __restrict__ bg,
                                                    const float* __restrict__ bq) {
    extern __shared__ char sm[];
    uint32_t sb0 = smem_u32(sm);
    const int tid = threadIdx.x, wid = tid >> 5, lane = tid & 31;
    const int g = lane >> 2, t = lane & 3;
    const int wm = (wid & 3) * 32, wn = (wid >> 2) * 32;
    const int bn = blockIdx.x * 64, bm = blockIdx.y * 128;

    const __nv_bfloat16* asrc[2] = { g_xh + (size_t)bm * E_, g_xl + (size_t)bm * E_ };
    const __nv_bfloat16* bsrc[6] = { g_wvh + (size_t)bn * E_, g_wvl + (size_t)bn * E_,
                                     g_wgh + (size_t)bn * E_, g_wgl + (size_t)bn * E_,
                                     g_wqh + (size_t)bn * E_, g_wql + (size_t)bn * E_ };

    float acc[3][2][4][4];
    #pragma unroll
    for (int a = 0; a < 3; a++)
        #pragma unroll
        for (int i = 0; i < 2; i++)
            #pragma unroll
            for (int j = 0; j < 4; j++)
                #pragma unroll
                for (int e = 0; e < 4; e++) acc[a][i][j][e] = 0.f;

    auto load_stage = [&](int kt, int stg) {
        uint32_t sb = sb0 + stg * ST3;
        int k0 = kt * 32;
        #pragma unroll
        for (int j = 0; j < 4; j++) {                 // A: 2 mats x 128 rows x 4 chunks
            int idx = tid + j * 256;
            int mat = idx >> 9, rem = idx & 511, r = rem >> 2, c = rem & 3;
            CP16(sb + mat * (128 * PADB) + r * PADB + c * 16,
                 asrc[mat] + (size_t)r * E_ + k0 + c * 8);
        }
        #pragma unroll
        for (int j = 0; j < 6; j++) {                 // B: 6 mats x 64 rows x 4 chunks
            int idx = tid + j * 256;
            int mat = idx >> 8, rem = idx & 255, r = rem >> 2, c = rem & 3;
            CP16(sb + 2 * 128 * PADB + mat * (64 * PADB) + r * PADB + c * 16,
                 bsrc[mat] + (size_t)r * E_ + k0 + c * 8);
        }
        CP_COMMIT();
    };

    load_stage(0, 0);
    load_stage(1, 1);
    CP_WAIT(1);
    __syncthreads();

    for (int kt = 0; kt < NKT3; kt++) {
        uint32_t sA = sb0 + (kt & 1) * ST3;
        uint32_t sB = sA + 2 * 128 * PADB;
        #pragma unroll
        for (int ks = 0; ks < 2; ks++) {
            int kb = ks * 32 + t * 4;                 // byte offset within row
            uint32_t a_h[2][4], a_l[2][4];
            #pragma unroll
            for (int mb = 0; mb < 2; mb++) {
                uint32_t base = sA + (wm + mb * 16 + g) * PADB + kb;
                a_h[mb][0] = lds32(base);
                a_h[mb][1] = lds32(base + 8 * PADB);
                a_h[mb][2] = lds32(base + 16);
                a_h[mb][3] = lds32(base + 8 * PADB + 16);
                uint32_t basel = base + 128 * PADB;
                a_l[mb][0] = lds32(basel);
                a_l[mb][1] = lds32(basel + 8 * PADB);
                a_l[mb][2] = lds32(basel + 16);
                a_l[mb][3] = lds32(basel + 8 * PADB + 16);
            }
            #pragma unroll
            for (int mat = 0; mat < 3; mat++) {
                uint32_t bh = sB + (2 * mat) * (64 * PADB);
                uint32_t bl = bh + 64 * PADB;
                uint32_t b_h[4][2], b_l[4][2];
                #pragma unroll
                for (int nb = 0; nb < 4; nb++) {
                    uint32_t ba = bh + (wn + nb * 8 + g) * PADB + kb;
                    b_h[nb][0] = lds32(ba);
                    b_h[nb][1] = lds32(ba + 16);
                    uint32_t bal = bl + (wn + nb * 8 + g) * PADB + kb;
                    b_l[nb][0] = lds32(bal);
                    b_l[nb][1] = lds32(bal + 16);
                }
                #pragma unroll
                for (int mb = 0; mb < 2; mb++)
                    #pragma unroll
                    for (int nb = 0; nb < 4; nb++) {
                        mma16816(acc[mat][mb][nb], a_h[mb], b_h[nb]);
                        mma16816(acc[mat][mb][nb], a_h[mb], b_l[nb]);
                        mma16816(acc[mat][mb][nb], a_l[mb], b_h[nb]);
                    }
            }
        }
        __syncthreads();
        if (kt + 2 < NKT3) {
            load_stage(kt + 2, kt & 1);
            CP_WAIT(1);
        } else {
            CP_WAIT(0);
        }
        __syncthreads();
    }

    // epilogue: store = v*sigmoid(g+bg)*scale ; que = sigmoid(q+bq)*scale
    #pragma unroll
    for (int mb = 0; mb < 2; mb++)
        #pragma unroll
        for (int nb = 0; nb < 4; nb++) {
            int col = bn + wn + nb * 8 + 2 * t;
            float bg0 = bg[col], bg1 = bg[col + 1];
            float bq0 = bq[col], bq1 = bq[col + 1];
            #pragma unroll
            for (int h = 0; h < 2; h++) {
                size_t row = (size_t)(bm + wm + mb * 16 + g + h * 8);
                float v0 = acc[0][mb][nb][2 * h], v1 = acc[0][mb][nb][2 * h + 1];
                float s0 = v0 * sigf(acc[1][mb][nb][2 * h]     + bg0) * SCALE_F;
                float s1 = v1 * sigf(acc[1][mb][nb][2 * h + 1] + bg1) * SCALE_F;
                float q0 = sigf(acc[2][mb][nb][2 * h]     + bq0) * SCALE_F;
                float q1 = sigf(acc[2][mb][nb][2 * h + 1] + bq1) * SCALE_F;
                *reinterpret_cast<float2*>(&g_store[row * M_ + col]) = make_float2(s0, s1);
                *reinterpret_cast<float2*>(&g_que[row * M_ + col])   = make_float2(q0, q1);
            }
        }
}

// ---------------- gemm_out: 128x128 tile ----------------
#define STO (4*128*PADB)                // 40960 bytes/stage
#define NKTO (M_ / 32)                  // 64
__global__ __launch_bounds__(256, 1) void gemm_out_mma(float* __restrict__ out) {
    extern __shared__ char sm[];
    uint32_t sb0 = smem_u32(sm);
    const int tid = threadIdx.x, wid = tid >> 5, lane = tid & 31;
    const int g = lane >> 2, t = lane & 3;
    const int wm = (wid & 3) * 32, wn = (wid >> 2) * 64;
    const int bn = blockIdx.x * 128, bm = blockIdx.y * 128;

    const __nv_bfloat16* srcs[4] = { g_ldh + (size_t)bm * M_, g_ldl + (size_t)bm * M_,
                                     g_woh + (size_t)bn * M_, g_wol + (size_t)bn * M_ };

    float acc[2][8][4];
    #pragma unroll
    for (int i = 0; i < 2; i++)
        #pragma unroll
        for (int j = 0; j < 8; j++)
            #pragma unroll
            for (int e = 0; e < 4; e++) acc[i][j][e] = 0.f;

    auto load_stage = [&](int kt, int stg) {
        uint32_t sb = sb0 + stg * STO;
        int k0 = kt * 32;
        #pragma unroll
        for (int j = 0; j < 8; j++) {
            int idx = tid + j * 256;
            int tile = idx >> 9, rem = idx & 511, r = rem >> 2, c = rem & 3;
            CP16(sb + tile * (128 * PADB) + r * PADB + c * 16,
                 srcs[tile] + (size_t)r * M_ + k0 + c * 8);
        }
        CP_COMMIT();
    };

    load_stage(0, 0);
    load_stage(1, 1);
    CP_WAIT(1);
    __syncthreads();

    for (int kt = 0; kt < NKTO; kt++) {
        uint32_t sb = sb0 + (kt & 1) * STO;
        #pragma unroll
        for (int ks = 0; ks < 2; ks++) {
            int kb = ks * 32 + t * 4;
            uint32_t a_h[2][4], a_l[2][4];
            #pragma unroll
            for (int mb = 0; mb < 2; mb++) {
                uint32_t base = sb + (wm + mb * 16 + g) * PADB + kb;
                a_h[mb][0] = lds32(base);
                a_h[mb][1] = lds32(base + 8 * PADB);
                a_h[mb][2] = lds32(base + 16);
                a_h[mb][3] = lds32(base + 8 * PADB + 16);
                uint32_t basel = base + 128 * PADB;
                a_l[mb][0] = lds32(basel);
                a_l[mb][1] = lds32(basel + 8 * PADB);
                a_l[mb][2] = lds32(basel + 16);
                a_l[mb][3] = lds32(basel + 8 * PADB + 16);
            }
            uint32_t bh0 = sb + 2 * 128 * PADB;
            uint32_t bl0 = sb + 3 * 128 * PADB;
            uint32_t b_h[8][2], b_l[8][2];
            #pragma unroll
            for (int nb = 0; nb < 8; nb++) {
                uint32_t ba = bh0 + (wn + nb * 8 + g) * PADB + kb;
                b_h[nb][0] = lds32(ba);
                b_h[nb][1] = lds32(ba + 16);
                uint32_t bal = bl0 + (wn + nb * 8 + g) * PADB + kb;
                b_l[nb][0] = lds32(bal);
                b_l[nb][1] = lds32(bal + 16);
            }
            #pragma unroll
            for (int mb = 0; mb < 2; mb++)
                #pragma unroll
                for (int nb = 0; nb < 8; nb++) {
                    mma16816(acc[mb][nb], a_h[mb], b_h[nb]);
                    mma16816(acc[mb][nb], a_h[mb], b_l[nb]);
                    mma16816(acc[mb][nb], a_l[mb], b_h[nb]);
                }
        }
        __syncthreads();
        if (kt + 2 < NKTO) {
            load_stage(kt + 2, kt & 1);
            CP_WAIT(1);
        } else {
            CP_WAIT(0);
        }
        __syncthreads();
    }

    #pragma unroll
    for (int mb = 0; mb < 2; mb++)
        #pragma unroll
        for (int nb = 0; nb < 8; nb++) {
            int col = bn + wn + nb * 8 + 2 * t;
            #pragma unroll
            for (int h = 0; h < 2; h++) {
                size_t row = (size_t)(bm + wm + mb * 16 + g + h * 8);
                *reinterpret_cast<float2*>(&out[row * E_ + col]) =
                    make_float2(acc[mb][nb][2 * h], acc[mb][nb][2 * h + 1]);
            }
        }
}

// ---------------- scan kernels ----------------
__global__ __launch_bounds__(128) void carry_kernel() {
    int m = blockIdx.x * 128 + threadIdx.x;
    int j = blockIdx.y, b = blockIdx.z;
    size_t base = ((size_t)(b * S_ + j * TS)) * M_ + m;
    float c = 0.f;
    #pragma unroll 8
    for (int t = 0; t < TS; t++)
        c = fmaf(DECAY_F, c, g_store[base + (size_t)t * M_]);
    g_carry[(size_t)(b * NT + j) * M_ + m] = c;
}

__global__ __launch_bounds__(256) void prefix_kernel() {
    int gid = blockIdx.x * blockDim.x + threadIdx.x;
    int b = gid / M_, m = gid % M_;
    float aTS = DECAY_F;
    #pragma unroll
    for (int i = 0; i < 8; i++) aTS *= aTS;          // 0.95^256
    float run = 0.f;
    #pragma unroll
    for (int j = 0; j < NT; j++) {
        size_t idx = (size_t)(b * NT + j) * M_ + m;
        g_prefix[idx] = run;
        run = g_carry[idx] + aTS * run;
    }
}

__global__ __launch_bounds__(128) void apply_kernel() {
    int m = blockIdx.x * 128 + threadIdx.x;
    int j = blockIdx.y, b = blockIdx.z;
    size_t base = ((size_t)(b * S_ + j * TS)) * M_ + m;
    float c = g_prefix[(size_t)(b * NT + j) * M_ + m];
    #pragma unroll 4
    for (int t = 0; t < TS; t++) {
        size_t idx = base + (size_t)t * M_;
        c = fmaf(DECAY_F, c, g_store[idx]);
        float v = c * g_que[idx];
        __nv_bfloat16 h = __float2bfloat16(v);
        g_ldh[idx] = h;
        g_ldl[idx] = __float2bfloat16(v - __bfloat162float(h));
    }
}

// ---------------- launch ----------------
extern "C" void kernel_launch(void* const* d_in, const int* in_sizes, int n_in,
                              void* d_out, int out_size) {
    const float* x  = (const float*)d_in[0];
    const float* Wv = (const float*)d_in[1];
    const float* Wg = (const float*)d_in[2];
    const float* bg = (const float*)d_in[3];
    const float* Wq = (const float*)d_in[4];
    const float* bq = (const float*)d_in[5];
    const float* Wo = (const float*)d_in[6];
    float* out = (float*)d_out;

    static bool attr_set = false;
    if (!attr_set) {
        cudaFuncSetAttribute(gemm3_mma, cudaFuncAttributeMaxDynamicSharedMemorySize, 2 * ST3);
        cudaFuncSetAttribute(gemm_out_mma, cudaFuncAttributeMaxDynamicSharedMemorySize, 2 * STO);
        attr_set = true;
    }

    __nv_bfloat16 *wvh, *wvl, *wgh, *wgl, *wqh, *wql, *woh, *wol;
    cudaGetSymbolAddress((void**)&wvh, g_wvh); cudaGetSymbolAddress((void**)&wvl, g_wvl);
    cudaGetSymbolAddress((void**)&wgh, g_wgh); cudaGetSymbolAddress((void**)&wgl, g_wgl);
    cudaGetSymbolAddress((void**)&wqh, g_wqh); cudaGetSymbolAddress((void**)&wql, g_wql);
    cudaGetSymbolAddress((void**)&woh, g_woh); cudaGetSymbolAddress((void**)&wol, g_wol);

    split_x_kernel<<<((size_t)N1 * E_ / 4) / 256, 256>>>(x);
    dim3 gt(M_ / 32, E_ / 32);
    tsplit_kernel<<<gt, 256>>>(Wv, wvh, wvl);
    tsplit_kernel<<<gt, 256>>>(Wg, wgh, wgl);
    tsplit_kernel<<<gt, 256>>>(Wq, wqh, wql);
    tsplit_kernel<<<gt, 256>>>(Wo, woh, wol);

    gemm3_mma<<<dim3(M_ / 64, N1 / 128), 256, 2 * ST3>>>(bg, bq);

    dim3 gscan(M_ / 128, NT, B_);
    carry_kernel<<<gscan, 128>>>();
    prefix_kernel<<<(B_ * M_) / 256, 256>>>();
    apply_kernel<<<gscan, 128>>>();

    gemm_out_mma<<<dim3(E_ / 128, N1 / 128), 256, 2 * STO>>>(out);
}

// round 4
// speedup vs baseline: 3.6695x; 1.5791x over previous
#include <cuda_runtime.h>
#include <cuda_fp16.h>
#include <cstdint>
#include <math.h>

#define B_   4
#define S_   4096
#define E_   2048
#define M_   2048
#define N1   (B_ * S_)
#define DECAY_F 0.95f
#define SCALE_F 0.22360679774997896f
#define TS   256
#define NT   (S_ / NT_DUMMY)
#undef NT
#define NT   (S_ / TS)

// ---------------- device scratch ----------------
__device__ float g_store[(size_t)N1 * M_];
__device__ float g_que  [(size_t)N1 * M_];
__device__ float g_carry [B_ * (S_ / TS) * M_];
__device__ float g_prefix[B_ * (S_ / TS) * M_];
__device__ __half g_xh[(size_t)N1 * E_], g_xl[(size_t)N1 * E_];
__device__ __half g_ldh[(size_t)N1 * M_], g_ldl[(size_t)N1 * M_];
__device__ __half g_wv[(size_t)E_ * M_];   // transposed [n][k] fp16
__device__ __half g_wg[(size_t)E_ * M_];
__device__ __half g_wq[(size_t)E_ * M_];
__device__ __half g_wo[(size_t)E_ * M_];

// ---------------- helpers ----------------
__device__ __forceinline__ uint32_t smem_u32(const void* p) {
    uint32_t a;
    asm("{ .reg .u64 t; cvta.to.shared.u64 t, %1; cvt.u32.u64 %0, t; }" : "=r"(a) : "l"(p));
    return a;
}
#define CP16(dst, src) \
    asm volatile("cp.async.cg.shared.global [%0], [%1], 16;" :: "r"(dst), "l"(src))
#define CP_COMMIT() asm volatile("cp.async.commit_group;" ::: "memory")
#define CP_WAIT(n)  asm volatile("cp.async.wait_group %0;" :: "n"(n) : "memory")

__device__ __forceinline__ uint32_t lds32(uint32_t addr) {
    uint32_t v;
    asm volatile("ld.shared.b32 %0, [%1];" : "=r"(v) : "r"(addr));
    return v;
}
__device__ __forceinline__ void mma16816(float* d, const uint32_t* a, const uint32_t* b) {
    asm volatile(
        "mma.sync.aligned.m16n8k16.row.col.f32.f16.f16.f32 "
        "{%0,%1,%2,%3}, {%4,%5,%6,%7}, {%8,%9}, {%0,%1,%2,%3};"
        : "+f"(d[0]), "+f"(d[1]), "+f"(d[2]), "+f"(d[3])
        : "r"(a[0]), "r"(a[1]), "r"(a[2]), "r"(a[3]), "r"(b[0]), "r"(b[1]));
}
__device__ __forceinline__ float sigf(float v) { return 1.0f / (1.0f + __expf(-v)); }

#define PADB 80   // 64B data + 16B pad per 32-elem K row: conflict-free frag loads

// ---------------- conversion kernels ----------------
__global__ __launch_bounds__(256) void split_x_kernel(const float* __restrict__ x) {
    size_t i = (size_t)blockIdx.x * 256 + threadIdx.x;
    float4 v = reinterpret_cast<const float4*>(x)[i];
    __half h0 = __float2half(v.x), h1 = __float2half(v.y);
    __half h2 = __float2half(v.z), h3 = __float2half(v.w);
    reinterpret_cast<__half2*>(g_xh)[2*i]   = __half2(h0, h1);
    reinterpret_cast<__half2*>(g_xh)[2*i+1] = __half2(h2, h3);
    reinterpret_cast<__half2*>(g_xl)[2*i] =
        __half2(__float2half(v.x - __half2float(h0)),
                __float2half(v.y - __half2float(h1)));
    reinterpret_cast<__half2*>(g_xl)[2*i+1] =
        __half2(__float2half(v.z - __half2float(h2)),
                __float2half(v.w - __half2float(h3)));
}

// W[k][n] -> T[n][k] fp16
__global__ __launch_bounds__(256) void tsplit_kernel(const float* __restrict__ W,
                                                     __half* __restrict__ Th) {
    __shared__ float tile[32][33];
    int bx = blockIdx.x * 32, by = blockIdx.y * 32;
    int tx = threadIdx.x & 31, ty = threadIdx.x >> 5;
    #pragma unroll
    for (int i = ty; i < 32; i += 8)
        tile[i][tx] = W[(size_t)(by + i) * M_ + bx + tx];
    __syncthreads();
    #pragma unroll
    for (int i = ty; i < 32; i += 8)
        Th[(size_t)(bx + i) * E_ + by + tx] = __float2half(tile[tx][i]);
}

// ---------------- gemm3: 128x(3x64) tile, fp16 mma, {2,1,1}-pass ----------------
#define ST3 ((2*128 + 3*64) * PADB)     // 35840 B/stage
#define NKT3 (E_ / 32)                  // 64
__global__ __launch_bounds__(256, 1) void gemm3_mma(const float* __restrict__ bg,
                                                    const float* __restrict__ bq) {
    extern __shared__ char sm[];
    uint32_t sb0 = smem_u32(sm);
    const int tid = threadIdx.x, wid = tid >> 5, lane = tid & 31;
    const int g = lane >> 2, t = lane & 3;
    const int wm = (wid & 3) * 32, wn = (wid >> 2) * 32;
    const int bn = blockIdx.x * 64, bm = blockIdx.y * 128;

    const __half* asrc[2] = { g_xh + (size_t)bm * E_, g_xl + (size_t)bm * E_ };
    const __half* bsrc[3] = { g_wv + (size_t)bn * E_, g_wg + (size_t)bn * E_,
                              g_wq + (size_t)bn * E_ };

    float acc[3][2][4][4];
    #pragma unroll
    for (int a = 0; a < 3; a++)
        #pragma unroll
        for (int i = 0; i < 2; i++)
            #pragma unroll
            for (int j = 0; j < 4; j++)
                #pragma unroll
                for (int e = 0; e < 4; e++) acc[a][i][j][e] = 0.f;

    auto load_stage = [&](int kt, int stg) {
        uint32_t sb = sb0 + stg * ST3;
        int k0 = kt * 32;
        #pragma unroll
        for (int j = 0; j < 4; j++) {                 // A: 2 mats x 128 rows x 4 chunks
            int idx = tid + j * 256;
            int mat = idx >> 9, rem = idx & 511, r = rem >> 2, c = rem & 3;
            CP16(sb + mat * (128 * PADB) + r * PADB + c * 16,
                 asrc[mat] + (size_t)r * E_ + k0 + c * 8);
        }
        #pragma unroll
        for (int j = 0; j < 3; j++) {                 // B: 3 mats x 64 rows x 4 chunks
            int idx = tid + j * 256;
            int mat = idx >> 8, rem = idx & 255, r = rem >> 2, c = rem & 3;
            CP16(sb + 2 * 128 * PADB + mat * (64 * PADB) + r * PADB + c * 16,
                 bsrc[mat] + (size_t)r * E_ + k0 + c * 8);
        }
        CP_COMMIT();
    };

    load_stage(0, 0);
    load_stage(1, 1);
    CP_WAIT(1);
    __syncthreads();

    for (int kt = 0; kt < NKT3; kt++) {
        uint32_t sA = sb0 + (kt & 1) * ST3;
        uint32_t sB = sA + 2 * 128 * PADB;
        #pragma unroll
        for (int ks = 0; ks < 2; ks++) {
            int kb = ks * 32 + t * 4;
            uint32_t a_h[2][4], a_l[2][4];
            #pragma unroll
            for (int mb = 0; mb < 2; mb++) {
                uint32_t base = sA + (wm + mb * 16 + g) * PADB + kb;
                a_h[mb][0] = lds32(base);
                a_h[mb][1] = lds32(base + 8 * PADB);
                a_h[mb][2] = lds32(base + 16);
                a_h[mb][3] = lds32(base + 8 * PADB + 16);
                uint32_t basel = base + 128 * PADB;
                a_l[mb][0] = lds32(basel);
                a_l[mb][1] = lds32(basel + 8 * PADB);
                a_l[mb][2] = lds32(basel + 16);
                a_l[mb][3] = lds32(basel + 8 * PADB + 16);
            }
            #pragma unroll
            for (int mat = 0; mat < 3; mat++) {
                uint32_t bb = sB + mat * (64 * PADB);
                uint32_t b_r[4][2];
                #pragma unroll
                for (int nb = 0; nb < 4; nb++) {
                    uint32_t ba = bb + (wn + nb * 8 + g) * PADB + kb;
                    b_r[nb][0] = lds32(ba);
                    b_r[nb][1] = lds32(ba + 16);
                }
                #pragma unroll
                for (int mb = 0; mb < 2; mb++)
                    #pragma unroll
                    for (int nb = 0; nb < 4; nb++) {
                        mma16816(acc[mat][mb][nb], a_h[mb], b_r[nb]);
                        if (mat == 0)   // value path: 2-pass
                            mma16816(acc[mat][mb][nb], a_l[mb], b_r[nb]);
                    }
            }
        }
        __syncthreads();
        if (kt + 2 < NKT3) {
            load_stage(kt + 2, kt & 1);
            CP_WAIT(1);
        } else {
            CP_WAIT(0);
        }
        __syncthreads();
    }

    #pragma unroll
    for (int mb = 0; mb < 2; mb++)
        #pragma unroll
        for (int nb = 0; nb < 4; nb++) {
            int col = bn + wn + nb * 8 + 2 * t;
            float bg0 = bg[col], bg1 = bg[col + 1];
            float bq0 = bq[col], bq1 = bq[col + 1];
            #pragma unroll
            for (int h = 0; h < 2; h++) {
                size_t row = (size_t)(bm + wm + mb * 16 + g + h * 8);
                float v0 = acc[0][mb][nb][2 * h], v1 = acc[0][mb][nb][2 * h + 1];
                float s0 = v0 * sigf(acc[1][mb][nb][2 * h]     + bg0) * SCALE_F;
                float s1 = v1 * sigf(acc[1][mb][nb][2 * h + 1] + bg1) * SCALE_F;
                float q0 = sigf(acc[2][mb][nb][2 * h]     + bq0) * SCALE_F;
                float q1 = sigf(acc[2][mb][nb][2 * h + 1] + bq1) * SCALE_F;
                *reinterpret_cast<float2*>(&g_store[row * M_ + col]) = make_float2(s0, s1);
                *reinterpret_cast<float2*>(&g_que[row * M_ + col])   = make_float2(q0, q1);
            }
        }
}

// ---------------- gemm_out: 128x128 tile, 2-pass ----------------
#define STO ((2*128 + 128) * PADB)      // 30720 B/stage
#define NKTO (M_ / 32)                  // 64
__global__ __launch_bounds__(256, 1) void gemm_out_mma(float* __restrict__ out) {
    extern __shared__ char sm[];
    uint32_t sb0 = smem_u32(sm);
    const int tid = threadIdx.x, wid = tid >> 5, lane = tid & 31;
    const int g = lane >> 2, t = lane & 3;
    const int wm = (wid & 3) * 32, wn = (wid >> 2) * 64;
    const int bn = blockIdx.x * 128, bm = blockIdx.y * 128;

    const __half* srcs[3] = { g_ldh + (size_t)bm * M_, g_ldl + (size_t)bm * M_,
                              g_wo + (size_t)bn * M_ };

    float acc[2][8][4];
    #pragma unroll
    for (int i = 0; i < 2; i++)
        #pragma unroll
        for (int j = 0; j < 8; j++)
            #pragma unroll
            for (int e = 0; e < 4; e++) acc[i][j][e] = 0.f;

    auto load_stage = [&](int kt, int stg) {
        uint32_t sb = sb0 + stg * STO;
        int k0 = kt * 32;
        #pragma unroll
        for (int j = 0; j < 6; j++) {                 // 3 tiles x 128 rows x 4 chunks
            int idx = tid + j * 256;
            int tile = idx >> 9, rem = idx & 511, r = rem >> 2, c = rem & 3;
            CP16(sb + tile * (128 * PADB) + r * PADB + c * 16,
                 srcs[tile] + (size_t)r * M_ + k0 + c * 8);
        }
        CP_COMMIT();
    };

    load_stage(0, 0);
    load_stage(1, 1);
    CP_WAIT(1);
    __syncthreads();

    for (int kt = 0; kt < NKTO; kt++) {
        uint32_t sb = sb0 + (kt & 1) * STO;
        #pragma unroll
        for (int ks = 0; ks < 2; ks++) {
            int kb = ks * 32 + t * 4;
            uint32_t a_h[2][4], a_l[2][4];
            #pragma unroll
            for (int mb = 0; mb < 2; mb++) {
                uint32_t base = sb + (wm + mb * 16 + g) * PADB + kb;
                a_h[mb][0] = lds32(base);
                a_h[mb][1] = lds32(base + 8 * PADB);
                a_h[mb][2] = lds32(base + 16);
                a_h[mb][3] = lds32(base + 8 * PADB + 16);
                uint32_t basel = base + 128 * PADB;
                a_l[mb][0] = lds32(basel);
                a_l[mb][1] = lds32(basel + 8 * PADB);
                a_l[mb][2] = lds32(basel + 16);
                a_l[mb][3] = lds32(basel + 8 * PADB + 16);
            }
            uint32_t b0 = sb + 2 * 128 * PADB;
            uint32_t b_r[8][2];
            #pragma unroll
            for (int nb = 0; nb < 8; nb++) {
                uint32_t ba = b0 + (wn + nb * 8 + g) * PADB + kb;
                b_r[nb][0] = lds32(ba);
                b_r[nb][1] = lds32(ba + 16);
            }
            #pragma unroll
            for (int mb = 0; mb < 2; mb++)
                #pragma unroll
                for (int nb = 0; nb < 8; nb++) {
                    mma16816(acc[mb][nb], a_h[mb], b_r[nb]);
                    mma16816(acc[mb][nb], a_l[mb], b_r[nb]);
                }
        }
        __syncthreads();
        if (kt + 2 < NKTO) {
            load_stage(kt + 2, kt & 1);
            CP_WAIT(1);
        } else {
            CP_WAIT(0);
        }
        __syncthreads();
    }

    #pragma unroll
    for (int mb = 0; mb < 2; mb++)
        #pragma unroll
        for (int nb = 0; nb < 8; nb++) {
            int col = bn + wn + nb * 8 + 2 * t;
            #pragma unroll
            for (int h = 0; h < 2; h++) {
                size_t row = (size_t)(bm + wm + mb * 16 + g + h * 8);
                *reinterpret_cast<float2*>(&out[row * E_ + col]) =
                    make_float2(acc[mb][nb][2 * h], acc[mb][nb][2 * h + 1]);
            }
        }
}

// ---------------- scan kernels ----------------
__global__ __launch_bounds__(128) void carry_kernel() {
    int m = blockIdx.x * 128 + threadIdx.x;
    int j = blockIdx.y, b = blockIdx.z;
    size_t base = ((size_t)(b * S_ + j * TS)) * M_ + m;
    float c = 0.f;
    #pragma unroll 8
    for (int t = 0; t < TS; t++)
        c = fmaf(DECAY_F, c, g_store[base + (size_t)t * M_]);
    g_carry[(size_t)(b * NT + j) * M_ + m] = c;
}

__global__ __launch_bounds__(256) void prefix_kernel() {
    int gid = blockIdx.x * blockDim.x + threadIdx.x;
    int b = gid / M_, m = gid % M_;
    float aTS = DECAY_F;
    #pragma unroll
    for (int i = 0; i < 8; i++) aTS *= aTS;          // 0.95^256
    float run = 0.f;
    #pragma unroll
    for (int j = 0; j < NT; j++) {
        size_t idx = (size_t)(b * NT + j) * M_ + m;
        g_prefix[idx] = run;
        run = g_carry[idx] + aTS * run;
    }
}

__global__ __launch_bounds__(128) void apply_kernel() {
    int m = blockIdx.x * 128 + threadIdx.x;
    int j = blockIdx.y, b = blockIdx.z;
    size_t base = ((size_t)(b * S_ + j * TS)) * M_ + m;
    float c = g_prefix[(size_t)(b * NT + j) * M_ + m];
    #pragma unroll 4
    for (int t = 0; t < TS; t++) {
        size_t idx = base + (size_t)t * M_;
        c = fmaf(DECAY_F, c, g_store[idx]);
        float v = c * g_que[idx];
        __half h = __float2half(v);
        g_ldh[idx] = h;
        g_ldl[idx] = __float2half(v - __half2float(h));
    }
}

// ---------------- launch ----------------
extern "C" void kernel_launch(void* const* d_in, const int* in_sizes, int n_in,
                              void* d_out, int out_size) {
    const float* x  = (const float*)d_in[0];
    const float* Wv = (const float*)d_in[1];
    const float* Wg = (const float*)d_in[2];
    const float* bg = (const float*)d_in[3];
    const float* Wq = (const float*)d_in[4];
    const float* bq = (const float*)d_in[5];
    const float* Wo = (const float*)d_in[6];
    float* out = (float*)d_out;

    cudaFuncSetAttribute(gemm3_mma, cudaFuncAttributeMaxDynamicSharedMemorySize, 2 * ST3);
    cudaFuncSetAttribute(gemm_out_mma, cudaFuncAttributeMaxDynamicSharedMemorySize, 2 * STO);

    __half *wv, *wg, *wq, *wo;
    cudaGetSymbolAddress((void**)&wv, g_wv);
    cudaGetSymbolAddress((void**)&wg, g_wg);
    cudaGetSymbolAddress((void**)&wq, g_wq);
    cudaGetSymbolAddress((void**)&wo, g_wo);

    split_x_kernel<<<((size_t)N1 * E_ / 4) / 256, 256>>>(x);
    dim3 gt(M_ / 32, E_ / 32);
    tsplit_kernel<<<gt, 256>>>(Wv, wv);
    tsplit_kernel<<<gt, 256>>>(Wg, wg);
    tsplit_kernel<<<gt, 256>>>(Wq, wq);
    tsplit_kernel<<<gt, 256>>>(Wo, wo);

    gemm3_mma<<<dim3(M_ / 64, N1 / 128), 256, 2 * ST3>>>(bg, bq);

    dim3 gscan(M_ / 128, NT, B_);
    carry_kernel<<<gscan, 128>>>();
    prefix_kernel<<<(B_ * M_) / 256, 256>>>();
    apply_kernel<<<gscan, 128>>>();

    gemm_out_mma<<<dim3(E_ / 128, N1 / 128), 256, 2 * STO>>>(out);
}

// round 5
// speedup vs baseline: 3.6748x; 1.0014x over previous
#include <cuda_runtime.h>
#include <cuda_fp16.h>
#include <cstdint>
#include <math.h>

#define B_   4
#define S_   4096
#define E_   2048
#define M_   2048
#define N1   (B_ * S_)
#define DECAY_F 0.95f
#define SCALE_F 0.22360679774997896f
#define TS   256
#define NT   (S_ / TS)

// ---------------- device scratch ----------------
__device__ float g_store[(size_t)N1 * M_];
__device__ float g_que  [(size_t)N1 * M_];
__device__ float g_carry [B_ * NT * M_];
__device__ float g_prefix[B_ * NT * M_];
__device__ __half g_xh[(size_t)N1 * E_], g_xl[(size_t)N1 * E_];
__device__ __half g_ldh[(size_t)N1 * M_], g_ldl[(size_t)N1 * M_];
__device__ __half g_wv[(size_t)E_ * M_];   // transposed [n][k] fp16
__device__ __half g_wg[(size_t)E_ * M_];
__device__ __half g_wq[(size_t)E_ * M_];
__device__ __half g_wo[(size_t)E_ * M_];

// ---------------- helpers ----------------
__device__ __forceinline__ uint32_t smem_u32(const void* p) {
    uint32_t a;
    asm("{ .reg .u64 t; cvta.to.shared.u64 t, %1; cvt.u32.u64 %0, t; }" : "=r"(a) : "l"(p));
    return a;
}
#define CP16(dst, src) \
    asm volatile("cp.async.cg.shared.global [%0], [%1], 16;" :: "r"(dst), "l"(src))
#define CP_COMMIT() asm volatile("cp.async.commit_group;" ::: "memory")
#define CP_WAIT(n)  asm volatile("cp.async.wait_group %0;" :: "n"(n) : "memory")

__device__ __forceinline__ void ldsm4(uint32_t* r, uint32_t addr) {
    asm volatile("ldmatrix.sync.aligned.m8n8.x4.shared.b16 {%0,%1,%2,%3}, [%4];"
        : "=r"(r[0]), "=r"(r[1]), "=r"(r[2]), "=r"(r[3]) : "r"(addr));
}
__device__ __forceinline__ void mma16816(float* d, const uint32_t* a, const uint32_t* b) {
    asm volatile(
        "mma.sync.aligned.m16n8k16.row.col.f32.f16.f16.f32 "
        "{%0,%1,%2,%3}, {%4,%5,%6,%7}, {%8,%9}, {%0,%1,%2,%3};"
        : "+f"(d[0]), "+f"(d[1]), "+f"(d[2]), "+f"(d[3])
        : "r"(a[0]), "r"(a[1]), "r"(a[2]), "r"(a[3]), "r"(b[0]), "r"(b[1]));
}
__device__ __forceinline__ float sigf(float v) { return 1.0f / (1.0f + __expf(-v)); }

#define PADB 80   // 64B data + 16B pad: scalar- AND ldmatrix-conflict-free

// ---------------- conversion kernels ----------------
__global__ __launch_bounds__(256) void split_x_kernel(const float* __restrict__ x) {
    size_t i = (size_t)blockIdx.x * 256 + threadIdx.x;
    float4 v = reinterpret_cast<const float4*>(x)[i];
    __half h0 = __float2half(v.x), h1 = __float2half(v.y);
    __half h2 = __float2half(v.z), h3 = __float2half(v.w);
    reinterpret_cast<__half2*>(g_xh)[2*i]   = __half2(h0, h1);
    reinterpret_cast<__half2*>(g_xh)[2*i+1] = __half2(h2, h3);
    reinterpret_cast<__half2*>(g_xl)[2*i] =
        __half2(__float2half(v.x - __half2float(h0)),
                __float2half(v.y - __half2float(h1)));
    reinterpret_cast<__half2*>(g_xl)[2*i+1] =
        __half2(__float2half(v.z - __half2float(h2)),
                __float2half(v.w - __half2float(h3)));
}

// W[k][n] -> T[n][k] fp16
__global__ __launch_bounds__(256) void tsplit_kernel(const float* __restrict__ W,
                                                     __half* __restrict__ Th) {
    __shared__ float tile[32][33];
    int bx = blockIdx.x * 32, by = blockIdx.y * 32;
    int tx = threadIdx.x & 31, ty = threadIdx.x >> 5;
    #pragma unroll
    for (int i = ty; i < 32; i += 8)
        tile[i][tx] = W[(size_t)(by + i) * M_ + bx + tx];
    __syncthreads();
    #pragma unroll
    for (int i = ty; i < 32; i += 8)
        Th[(size_t)(bx + i) * E_ + by + tx] = __float2half(tile[tx][i]);
}

// ---------------- gemm3: 128x(3x64) tile, fp16 mma, {2,1,1}-pass ----------------
#define ST3 ((2*128 + 3*64) * PADB)     // 35840 B/stage
#define NKT3 (E_ / 32)                  // 64
__global__ __launch_bounds__(256, 1) void gemm3_mma(const float* __restrict__ bg,
                                                    const float* __restrict__ bq) {
    extern __shared__ char sm[];
    uint32_t sb0 = smem_u32(sm);
    const int tid = threadIdx.x, wid = tid >> 5, lane = tid & 31;
    const int g = lane >> 2, t = lane & 3;
    const int wm = (wid & 3) * 32, wn = (wid >> 2) * 32;
    const int bn = blockIdx.x * 64, bm = blockIdx.y * 128;
    // ldmatrix lane addressing
    const int lrow = lane & 15;                 // row within 16-row frag
    const int lcol = (lane >> 4) << 4;          // 0 or 16 bytes (k half)

    const __half* asrc[2] = { g_xh + (size_t)bm * E_, g_xl + (size_t)bm * E_ };
    const __half* bsrc[3] = { g_wv + (size_t)bn * E_, g_wg + (size_t)bn * E_,
                              g_wq + (size_t)bn * E_ };

    float acc[3][2][4][4];
    #pragma unroll
    for (int a = 0; a < 3; a++)
        #pragma unroll
        for (int i = 0; i < 2; i++)
            #pragma unroll
            for (int j = 0; j < 4; j++)
                #pragma unroll
                for (int e = 0; e < 4; e++) acc[a][i][j][e] = 0.f;

    auto load_stage = [&](int kt, int stg) {
        uint32_t sb = sb0 + stg * ST3;
        int k0 = kt * 32;
        #pragma unroll
        for (int j = 0; j < 4; j++) {                 // A: 2 mats x 128 rows x 4 chunks
            int idx = tid + j * 256;
            int mat = idx >> 9, rem = idx & 511, r = rem >> 2, c = rem & 3;
            CP16(sb + mat * (128 * PADB) + r * PADB + c * 16,
                 asrc[mat] + (size_t)r * E_ + k0 + c * 8);
        }
        #pragma unroll
        for (int j = 0; j < 3; j++) {                 // B: 3 mats x 64 rows x 4 chunks
            int idx = tid + j * 256;
            int mat = idx >> 8, rem = idx & 255, r = rem >> 2, c = rem & 3;
            CP16(sb + 2 * 128 * PADB + mat * (64 * PADB) + r * PADB + c * 16,
                 bsrc[mat] + (size_t)r * E_ + k0 + c * 8);
        }
        CP_COMMIT();
    };

    load_stage(0, 0);
    load_stage(1, 1);
    CP_WAIT(1);
    __syncthreads();

    for (int kt = 0; kt < NKT3; kt++) {
        uint32_t sA = sb0 + (kt & 1) * ST3;
        uint32_t sB = sA + 2 * 128 * PADB;
        uint32_t aRow = sA + (wm + lrow) * PADB + lcol;          // A hi base
        uint32_t bRow = sB + (wn + lrow) * PADB + lcol;          // B base (per-mat offset added)
        #pragma unroll
        for (int ks = 0; ks < 2; ks++) {
            int co = ks * 32;
            uint32_t a_h[2][4], a_l[2][4];
            #pragma unroll
            for (int mb = 0; mb < 2; mb++) {
                ldsm4(a_h[mb], aRow + mb * (16 * PADB) + co);
                ldsm4(a_l[mb], aRow + 128 * PADB + mb * (16 * PADB) + co);
            }
            #pragma unroll
            for (int mat = 0; mat < 3; mat++) {
                #pragma unroll
                for (int p = 0; p < 2; p++) {         // nb pair {2p, 2p+1}
                    uint32_t br[4];
                    ldsm4(br, bRow + mat * (64 * PADB) + p * (16 * PADB) + co);
                    uint32_t b0[2] = { br[0], br[2] };
                    uint32_t b1[2] = { br[1], br[3] };
                    #pragma unroll
                    for (int mb = 0; mb < 2; mb++) {
                        mma16816(acc[mat][mb][2 * p],     a_h[mb], b0);
                        mma16816(acc[mat][mb][2 * p + 1], a_h[mb], b1);
                        if (mat == 0) {               // value path: 2-pass
                            mma16816(acc[mat][mb][2 * p],     a_l[mb], b0);
                            mma16816(acc[mat][mb][2 * p + 1], a_l[mb], b1);
                        }
                    }
                }
            }
        }
        __syncthreads();
        if (kt + 2 < NKT3) {
            load_stage(kt + 2, kt & 1);
            CP_WAIT(1);
        } else {
            CP_WAIT(0);
        }
        __syncthreads();
    }

    #pragma unroll
    for (int mb = 0; mb < 2; mb++)
        #pragma unroll
        for (int nb = 0; nb < 4; nb++) {
            int col = bn + wn + nb * 8 + 2 * t;
            float bg0 = bg[col], bg1 = bg[col + 1];
            float bq0 = bq[col], bq1 = bq[col + 1];
            #pragma unroll
            for (int h = 0; h < 2; h++) {
                size_t row = (size_t)(bm + wm + mb * 16 + g + h * 8);
                float v0 = acc[0][mb][nb][2 * h], v1 = acc[0][mb][nb][2 * h + 1];
                float s0 = v0 * sigf(acc[1][mb][nb][2 * h]     + bg0) * SCALE_F;
                float s1 = v1 * sigf(acc[1][mb][nb][2 * h + 1] + bg1) * SCALE_F;
                float q0 = sigf(acc[2][mb][nb][2 * h]     + bq0) * SCALE_F;
                float q1 = sigf(acc[2][mb][nb][2 * h + 1] + bq1) * SCALE_F;
                *reinterpret_cast<float2*>(&g_store[row * M_ + col]) = make_float2(s0, s1);
                *reinterpret_cast<float2*>(&g_que[row * M_ + col])   = make_float2(q0, q1);
            }
        }
}

// ---------------- gemm_out: 128x128 tile, 2-pass ----------------
#define STO ((2*128 + 128) * PADB)      // 30720 B/stage
#define NKTO (M_ / 32)                  // 64
__global__ __launch_bounds__(256, 1) void gemm_out_mma(float* __restrict__ out) {
    extern __shared__ char sm[];
    uint32_t sb0 = smem_u32(sm);
    const int tid = threadIdx.x, wid = tid >> 5, lane = tid & 31;
    const int g = lane >> 2, t = lane & 3;
    const int wm = (wid & 3) * 32, wn = (wid >> 2) * 64;
    const int bn = blockIdx.x * 128, bm = blockIdx.y * 128;
    const int lrow = lane & 15;
    const int lcol = (lane >> 4) << 4;

    const __half* srcs[3] = { g_ldh + (size_t)bm * M_, g_ldl + (size_t)bm * M_,
                              g_wo + (size_t)bn * M_ };

    float acc[2][8][4];
    #pragma unroll
    for (int i = 0; i < 2; i++)
        #pragma unroll
        for (int j = 0; j < 8; j++)
            #pragma unroll
            for (int e = 0; e < 4; e++) acc[i][j][e] = 0.f;

    auto load_stage = [&](int kt, int stg) {
        uint32_t sb = sb0 + stg * STO;
        int k0 = kt * 32;
        #pragma unroll
        for (int j = 0; j < 6; j++) {                 // 3 tiles x 128 rows x 4 chunks
            int idx = tid + j * 256;
            int tile = idx >> 9, rem = idx & 511, r = rem >> 2, c = rem & 3;
            CP16(sb + tile * (128 * PADB) + r * PADB + c * 16,
                 srcs[tile] + (size_t)r * M_ + k0 + c * 8);
        }
        CP_COMMIT();
    };

    load_stage(0, 0);
    load_stage(1, 1);
    CP_WAIT(1);
    __syncthreads();

    for (int kt = 0; kt < NKTO; kt++) {
        uint32_t sb = sb0 + (kt & 1) * STO;
        uint32_t aRow = sb + (wm + lrow) * PADB + lcol;
        uint32_t bRow = sb + 2 * 128 * PADB + (wn + lrow) * PADB + lcol;
        #pragma unroll
        for (int ks = 0; ks < 2; ks++) {
            int co = ks * 32;
            uint32_t a_h[2][4], a_l[2][4];
            #pragma unroll
            for (int mb = 0; mb < 2; mb++) {
                ldsm4(a_h[mb], aRow + mb * (16 * PADB) + co);
                ldsm4(a_l[mb], aRow + 128 * PADB + mb * (16 * PADB) + co);
            }
            #pragma unroll
            for (int p = 0; p < 4; p++) {             // nb pair {2p, 2p+1}
                uint32_t br[4];
                ldsm4(br, bRow + p * (16 * PADB) + co);
                uint32_t b0[2] = { br[0], br[2] };
                uint32_t b1[2] = { br[1], br[3] };
                #pragma unroll
                for (int mb = 0; mb < 2; mb++) {
                    mma16816(acc[mb][2 * p],     a_h[mb], b0);
                    mma16816(acc[mb][2 * p + 1], a_h[mb], b1);
                    mma16816(acc[mb][2 * p],     a_l[mb], b0);
                    mma16816(acc[mb][2 * p + 1], a_l[mb], b1);
                }
            }
        }
        __syncthreads();
        if (kt + 2 < NKTO) {
            load_stage(kt + 2, kt & 1);
            CP_WAIT(1);
        } else {
            CP_WAIT(0);
        }
        __syncthreads();
    }

    #pragma unroll
    for (int mb = 0; mb < 2; mb++)
        #pragma unroll
        for (int nb = 0; nb < 8; nb++) {
            int col = bn + wn + nb * 8 + 2 * t;
            #pragma unroll
            for (int h = 0; h < 2; h++) {
                size_t row = (size_t)(bm + wm + mb * 16 + g + h * 8);
                *reinterpret_cast<float2*>(&out[row * E_ + col]) =
                    make_float2(acc[mb][nb][2 * h], acc[mb][nb][2 * h + 1]);
            }
        }
}

// ---------------- scan kernels ----------------
__global__ __launch_bounds__(128) void carry_kernel() {
    int m = blockIdx.x * 128 + threadIdx.x;
    int j = blockIdx.y, b = blockIdx.z;
    size_t base = ((size_t)(b * S_ + j * TS)) * M_ + m;
    float c = 0.f;
    #pragma unroll 8
    for (int t = 0; t < TS; t++)
        c = fmaf(DECAY_F, c, g_store[base + (size_t)t * M_]);
    g_carry[(size_t)(b * NT + j) * M_ + m] = c;
}

__global__ __launch_bounds__(256) void prefix_kernel() {
    int gid = blockIdx.x * blockDim.x + threadIdx.x;
    int b = gid / M_, m = gid % M_;
    float aTS = DECAY_F;
    #pragma unroll
    for (int i = 0; i < 8; i++) aTS *= aTS;          // 0.95^256
    float run = 0.f;
    #pragma unroll
    for (int j = 0; j < NT; j++) {
        size_t idx = (size_t)(b * NT + j) * M_ + m;
        g_prefix[idx] = run;
        run = g_carry[idx] + aTS * run;
    }
}

__global__ __launch_bounds__(128) void apply_kernel() {
    int m = blockIdx.x * 128 + threadIdx.x;
    int j = blockIdx.y, b = blockIdx.z;
    size_t base = ((size_t)(b * S_ + j * TS)) * M_ + m;
    float c = g_prefix[(size_t)(b * NT + j) * M_ + m];
    #pragma unroll 4
    for (int t = 0; t < TS; t++) {
        size_t idx = base + (size_t)t * M_;
        c = fmaf(DECAY_F, c, g_store[idx]);
        float v = c * g_que[idx];
        __half h = __float2half(v);
        g_ldh[idx] = h;
        g_ldl[idx] = __float2half(v - __half2float(h));
    }
}

// ---------------- launch ----------------
extern "C" void kernel_launch(void* const* d_in, const int* in_sizes, int n_in,
                              void* d_out, int out_size) {
    const float* x  = (const float*)d_in[0];
    const float* Wv = (const float*)d_in[1];
    const float* Wg = (const float*)d_in[2];
    const float* bg = (const float*)d_in[3];
    const float* Wq = (const float*)d_in[4];
    const float* bq = (const float*)d_in[5];
    const float* Wo = (const float*)d_in[6];
    float* out = (float*)d_out;

    cudaFuncSetAttribute(gemm3_mma, cudaFuncAttributeMaxDynamicSharedMemorySize, 2 * ST3);
    cudaFuncSetAttribute(gemm_out_mma, cudaFuncAttributeMaxDynamicSharedMemorySize, 2 * STO);

    __half *wv, *wg, *wq, *wo;
    cudaGetSymbolAddress((void**)&wv, g_wv);
    cudaGetSymbolAddress((void**)&wg, g_wg);
    cudaGetSymbolAddress((void**)&wq, g_wq);
    cudaGetSymbolAddress((void**)&wo, g_wo);

    split_x_kernel<<<((size_t)N1 * E_ / 4) / 256, 256>>>(x);
    dim3 gt(M_ / 32, E_ / 32);
    tsplit_kernel<<<gt, 256>>>(Wv, wv);
    tsplit_kernel<<<gt, 256>>>(Wg, wg);
    tsplit_kernel<<<gt, 256>>>(Wq, wq);
    tsplit_kernel<<<gt, 256>>>(Wo, wo);

    gemm3_mma<<<dim3(M_ / 64, N1 / 128), 256, 2 * ST3>>>(bg, bq);

    dim3 gscan(M_ / 128, NT, B_);
    carry_kernel<<<gscan, 128>>>();
    prefix_kernel<<<(B_ * M_) / 256, 256>>>();
    apply_kernel<<<gscan, 128>>>();

    gemm_out_mma<<<dim3(E_ / 128, N1 / 128), 256, 2 * STO>>>(out);
}

// round 6
// speedup vs baseline: 4.0335x; 1.0976x over previous
#include <cuda_runtime.h>
#include <cuda_fp16.h>
#include <cstdint>
#include <math.h>

#define B_   4
#define S_   4096
#define E_   2048
#define M_   2048
#define N1   (B_ * S_)
#define DECAY_F 0.95f
#define SCALE_F 0.22360679774997896f
#define TS   256
#define NT   (S_ / TS)

// ---------------- device scratch ----------------
__device__ float g_v[(size_t)N1 * M_];     // raw x@Wv
__device__ float g_g[(size_t)N1 * M_];     // raw x@Wg
__device__ float g_q[(size_t)N1 * M_];     // raw x@Wq
__device__ float g_carry [B_ * NT * M_];
__device__ float g_prefix[B_ * NT * M_];
__device__ __half g_xh[(size_t)N1 * E_];
__device__ __half g_ldh[(size_t)N1 * M_], g_ldl[(size_t)N1 * M_];
__device__ __half g_wv[(size_t)E_ * M_];   // transposed [n][k] fp16
__device__ __half g_wg[(size_t)E_ * M_];
__device__ __half g_wq[(size_t)E_ * M_];
__device__ __half g_wo[(size_t)E_ * M_];

// ---------------- helpers ----------------
__device__ __forceinline__ uint32_t smem_u32(const void* p) {
    uint32_t a;
    asm("{ .reg .u64 t; cvta.to.shared.u64 t, %1; cvt.u32.u64 %0, t; }" : "=r"(a) : "l"(p));
    return a;
}
#define CP16(dst, src) \
    asm volatile("cp.async.cg.shared.global [%0], [%1], 16;" :: "r"(dst), "l"(src))
#define CP_COMMIT() asm volatile("cp.async.commit_group;" ::: "memory")
#define CP_WAIT(n)  asm volatile("cp.async.wait_group %0;" :: "n"(n) : "memory")

__device__ __forceinline__ void ldsm4(uint32_t* r, uint32_t addr) {
    asm volatile("ldmatrix.sync.aligned.m8n8.x4.shared.b16 {%0,%1,%2,%3}, [%4];"
        : "=r"(r[0]), "=r"(r[1]), "=r"(r[2]), "=r"(r[3]) : "r"(addr));
}
__device__ __forceinline__ void mma16816(float* d, const uint32_t* a, const uint32_t* b) {
    asm volatile(
        "mma.sync.aligned.m16n8k16.row.col.f32.f16.f16.f32 "
        "{%0,%1,%2,%3}, {%4,%5,%6,%7}, {%8,%9}, {%0,%1,%2,%3};"
        : "+f"(d[0]), "+f"(d[1]), "+f"(d[2]), "+f"(d[3])
        : "r"(a[0]), "r"(a[1]), "r"(a[2]), "r"(a[3]), "r"(b[0]), "r"(b[1]));
}
__device__ __forceinline__ float sigf(float v) { return 1.0f / (1.0f + __expf(-v)); }

#define PADB 80   // 64B data + 16B pad: ldmatrix-conflict-free row stride

// ---------------- conversion kernels ----------------
__global__ __launch_bounds__(256) void split_x_kernel(const float* __restrict__ x) {
    size_t i = (size_t)blockIdx.x * 256 + threadIdx.x;
    float4 v = reinterpret_cast<const float4*>(x)[i];
    reinterpret_cast<__half2*>(g_xh)[2*i] =
        __half2(__float2half(v.x), __float2half(v.y));
    reinterpret_cast<__half2*>(g_xh)[2*i+1] =
        __half2(__float2half(v.z), __float2half(v.w));
}

// W[k][n] -> T[n][k] fp16
__global__ __launch_bounds__(256) void tsplit_kernel(const float* __restrict__ W,
                                                     __half* __restrict__ Th) {
    __shared__ float tile[32][33];
    int bx = blockIdx.x * 32, by = blockIdx.y * 32;
    int tx = threadIdx.x & 31, ty = threadIdx.x >> 5;
    #pragma unroll
    for (int i = ty; i < 32; i += 8)
        tile[i][tx] = W[(size_t)(by + i) * M_ + bx + tx];
    __syncthreads();
    #pragma unroll
    for (int i = ty; i < 32; i += 8)
        Th[(size_t)(bx + i) * E_ + by + tx] = __float2half(tile[tx][i]);
}

// ---------------- gemm3: 128m x 192n (3 mats), warp 64m x 48n ----------------
#define ST3 ((128 + 192) * PADB)        // 25600 B/stage
#define NKT3 (E_ / 32)                  // 64
__global__ __launch_bounds__(256, 1) void gemm3_mma() {
    extern __shared__ char sm[];
    uint32_t sb0 = smem_u32(sm);
    const int tid = threadIdx.x, wid = tid >> 5, lane = tid & 31;
    const int g = lane >> 2, t = lane & 3;
    const int wm = (wid & 1) * 64, wn = (wid >> 1) * 48;
    const int bn = blockIdx.x * 64, bm = blockIdx.y * 128;
    const int lrow = lane & 15;
    const int lcol = (lane >> 4) << 4;

    const __half* asrc = g_xh + (size_t)bm * E_;
    const __half* bsrc[3] = { g_wv + (size_t)bn * E_, g_wg + (size_t)bn * E_,
                              g_wq + (size_t)bn * E_ };

    float acc[4][6][4];
    #pragma unroll
    for (int i = 0; i < 4; i++)
        #pragma unroll
        for (int j = 0; j < 6; j++)
            #pragma unroll
            for (int e = 0; e < 4; e++) acc[i][j][e] = 0.f;

    auto load_stage = [&](int kt, int stg) {
        uint32_t sb = sb0 + stg * ST3;
        int k0 = kt * 32;
        #pragma unroll
        for (int j = 0; j < 5; j++) {                 // 1280 CP16 total
            int idx = tid + j * 256;
            if (idx < 512) {                          // A: 128 rows x 4 chunks
                int r = idx >> 2, c = idx & 3;
                CP16(sb + r * PADB + c * 16, asrc + (size_t)r * E_ + k0 + c * 8);
            } else {                                  // B: 192 rows x 4 chunks
                int rem = idx - 512;
                int r = rem >> 2, c = rem & 3;
                int mat = r >> 6, nrow = r & 63;
                CP16(sb + (128 + r) * PADB + c * 16,
                     bsrc[mat] + (size_t)nrow * E_ + k0 + c * 8);
            }
        }
    };

    load_stage(0, 0); CP_COMMIT();
    load_stage(1, 1); CP_COMMIT();
    CP_WAIT(1);
    __syncthreads();

    for (int kt = 0; kt < NKT3; kt++) {
        int stg = kt % 3;
        uint32_t sA = sb0 + stg * ST3;
        uint32_t sB = sA + 128 * PADB;
        uint32_t aRow = sA + (wm + lrow) * PADB + lcol;
        uint32_t bRow = sB + (wn + lrow) * PADB + lcol;

        if (kt + 2 < NKT3) load_stage(kt + 2, (kt + 2) % 3);
        CP_COMMIT();

        #pragma unroll
        for (int ks = 0; ks < 2; ks++) {
            int co = ks * 32;
            uint32_t a[4][4];
            #pragma unroll
            for (int mb = 0; mb < 4; mb++)
                ldsm4(a[mb], aRow + mb * (16 * PADB) + co);
            #pragma unroll
            for (int p = 0; p < 3; p++) {             // nb pairs {0,1},{2,3},{4,5}
                uint32_t br[4];
                ldsm4(br, bRow + p * (16 * PADB) + co);
                uint32_t b0[2] = { br[0], br[2] };
                uint32_t b1[2] = { br[1], br[3] };
                #pragma unroll
                for (int mb = 0; mb < 4; mb++) {
                    mma16816(acc[mb][2 * p],     a[mb], b0);
                    mma16816(acc[mb][2 * p + 1], a[mb], b1);
                }
            }
        }
        CP_WAIT(1);
        __syncthreads();
    }

    // raw outputs: route each 8-col block to its matrix's array
    #pragma unroll
    for (int mb = 0; mb < 4; mb++)
        #pragma unroll
        for (int nb = 0; nb < 6; nb++) {
            int c192 = wn + nb * 8 + 2 * t;           // col in [0,192)
            int mat = c192 >> 6;
            int mcol = bn + (c192 & 63);
            float* arr = (mat == 0) ? g_v : (mat == 1) ? g_g : g_q;
            #pragma unroll
            for (int h = 0; h < 2; h++) {
                size_t row = (size_t)(bm + wm + mb * 16 + g + h * 8);
                *reinterpret_cast<float2*>(&arr[row * M_ + mcol]) =
                    make_float2(acc[mb][nb][2 * h], acc[mb][nb][2 * h + 1]);
            }
        }
}

// ---------------- gemm_out: 128m x 128n, warp 64m x 32n, 2-pass ----------------
#define STO ((2*128 + 128) * PADB)      // 30720 B/stage
#define NKTO (M_ / 32)                  // 64
__global__ __launch_bounds__(256, 1) void gemm_out_mma(float* __restrict__ out) {
    extern __shared__ char sm[];
    uint32_t sb0 = smem_u32(sm);
    const int tid = threadIdx.x, wid = tid >> 5, lane = tid & 31;
    const int g = lane >> 2, t = lane & 3;
    const int wm = (wid & 1) * 64, wn = (wid >> 1) * 32;
    const int bn = blockIdx.x * 128, bm = blockIdx.y * 128;
    const int lrow = lane & 15;
    const int lcol = (lane >> 4) << 4;

    const __half* srcs[3] = { g_ldh + (size_t)bm * M_, g_ldl + (size_t)bm * M_,
                              g_wo + (size_t)bn * M_ };

    float acc[4][4][4];
    #pragma unroll
    for (int i = 0; i < 4; i++)
        #pragma unroll
        for (int j = 0; j < 4; j++)
            #pragma unroll
            for (int e = 0; e < 4; e++) acc[i][j][e] = 0.f;

    auto load_stage = [&](int kt, int stg) {
        uint32_t sb = sb0 + stg * STO;
        int k0 = kt * 32;
        #pragma unroll
        for (int j = 0; j < 6; j++) {                 // 3 tiles x 128 rows x 4 chunks
            int idx = tid + j * 256;
            int tile = idx >> 9, rem = idx & 511, r = rem >> 2, c = rem & 3;
            CP16(sb + tile * (128 * PADB) + r * PADB + c * 16,
                 srcs[tile] + (size_t)r * M_ + k0 + c * 8);
        }
    };

    load_stage(0, 0); CP_COMMIT();
    load_stage(1, 1); CP_COMMIT();
    CP_WAIT(1);
    __syncthreads();

    for (int kt = 0; kt < NKTO; kt++) {
        int stg = kt % 3;
        uint32_t sb = sb0 + stg * STO;
        uint32_t aRow = sb + (wm + lrow) * PADB + lcol;
        uint32_t bRow = sb + 2 * 128 * PADB + (wn + lrow) * PADB + lcol;

        if (kt + 2 < NKTO) load_stage(kt + 2, (kt + 2) % 3);
        CP_COMMIT();

        #pragma unroll
        for (int ks = 0; ks < 2; ks++) {
            int co = ks * 32;
            uint32_t a_h[4][4], a_l[4][4];
            #pragma unroll
            for (int mb = 0; mb < 4; mb++) {
                ldsm4(a_h[mb], aRow + mb * (16 * PADB) + co);
                ldsm4(a_l[mb], aRow + 128 * PADB + mb * (16 * PADB) + co);
            }
            #pragma unroll
            for (int p = 0; p < 2; p++) {             // nb pairs {0,1},{2,3}
                uint32_t br[4];
                ldsm4(br, bRow + p * (16 * PADB) + co);
                uint32_t b0[2] = { br[0], br[2] };
                uint32_t b1[2] = { br[1], br[3] };
                #pragma unroll
                for (int mb = 0; mb < 4; mb++) {
                    mma16816(acc[mb][2 * p],     a_h[mb], b0);
                    mma16816(acc[mb][2 * p + 1], a_h[mb], b1);
                    mma16816(acc[mb][2 * p],     a_l[mb], b0);
                    mma16816(acc[mb][2 * p + 1], a_l[mb], b1);
                }
            }
        }
        CP_WAIT(1);
        __syncthreads();
    }

    #pragma unroll
    for (int mb = 0; mb < 4; mb++)
        #pragma unroll
        for (int nb = 0; nb < 4; nb++) {
            int col = bn + wn + nb * 8 + 2 * t;
            #pragma unroll
            for (int h = 0; h < 2; h++) {
                size_t row = (size_t)(bm + wm + mb * 16 + g + h * 8);
                *reinterpret_cast<float2*>(&out[row * E_ + col]) =
                    make_float2(acc[mb][nb][2 * h], acc[mb][nb][2 * h + 1]);
            }
        }
}

// ---------------- scan kernels (gating fused) ----------------
__global__ __launch_bounds__(128) void carry_kernel(const float* __restrict__ bg) {
    int m = blockIdx.x * 128 + threadIdx.x;
    int j = blockIdx.y, b = blockIdx.z;
    size_t base = ((size_t)(b * S_ + j * TS)) * M_ + m;
    float bgm = bg[m];
    float c = 0.f;
    #pragma unroll 4
    for (int t = 0; t < TS; t++) {
        size_t idx = base + (size_t)t * M_;
        float s = g_v[idx] * sigf(g_g[idx] + bgm) * SCALE_F;
        c = fmaf(DECAY_F, c, s);
    }
    g_carry[(size_t)(b * NT + j) * M_ + m] = c;
}

__global__ __launch_bounds__(256) void prefix_kernel() {
    int gid = blockIdx.x * blockDim.x + threadIdx.x;
    int b = gid / M_, m = gid % M_;
    float aTS = DECAY_F;
    #pragma unroll
    for (int i = 0; i < 8; i++) aTS *= aTS;          // 0.95^256
    float run = 0.f;
    #pragma unroll
    for (int j = 0; j < NT; j++) {
        size_t idx = (size_t)(b * NT + j) * M_ + m;
        g_prefix[idx] = run;
        run = g_carry[idx] + aTS * run;
    }
}

__global__ __launch_bounds__(128) void apply_kernel(const float* __restrict__ bg,
                                                    const float* __restrict__ bq) {
    int m = blockIdx.x * 128 + threadIdx.x;
    int j = blockIdx.y, b = blockIdx.z;
    size_t base = ((size_t)(b * S_ + j * TS)) * M_ + m;
    float bgm = bg[m], bqm = bq[m];
    float c = g_prefix[(size_t)(b * NT + j) * M_ + m];
    #pragma unroll 4
    for (int t = 0; t < TS; t++) {
        size_t idx = base + (size_t)t * M_;
        float s = g_v[idx] * sigf(g_g[idx] + bgm) * SCALE_F;
        c = fmaf(DECAY_F, c, s);
        float que = sigf(g_q[idx] + bqm) * SCALE_F;
        float v = c * que;
        __half h = __float2half(v);
        g_ldh[idx] = h;
        g_ldl[idx] = __float2half(v - __half2float(h));
    }
}

// ---------------- launch ----------------
extern "C" void kernel_launch(void* const* d_in, const int* in_sizes, int n_in,
                              void* d_out, int out_size) {
    const float* x  = (const float*)d_in[0];
    const float* Wv = (const float*)d_in[1];
    const float* Wg = (const float*)d_in[2];
    const float* bg = (const float*)d_in[3];
    const float* Wq = (const float*)d_in[4];
    const float* bq = (const float*)d_in[5];
    const float* Wo = (const float*)d_in[6];
    float* out = (float*)d_out;

    cudaFuncSetAttribute(gemm3_mma, cudaFuncAttributeMaxDynamicSharedMemorySize, 3 * ST3);
    cudaFuncSetAttribute(gemm_out_mma, cudaFuncAttributeMaxDynamicSharedMemorySize, 3 * STO);

    __half *wv, *wg, *wq, *wo;
    cudaGetSymbolAddress((void**)&wv, g_wv);
    cudaGetSymbolAddress((void**)&wg, g_wg);
    cudaGetSymbolAddress((void**)&wq, g_wq);
    cudaGetSymbolAddress((void**)&wo, g_wo);

    split_x_kernel<<<((size_t)N1 * E_ / 4) / 256, 256>>>(x);
    dim3 gt(M_ / 32, E_ / 32);
    tsplit_kernel<<<gt, 256>>>(Wv, wv);
    tsplit_kernel<<<gt, 256>>>(Wg, wg);
    tsplit_kernel<<<gt, 256>>>(Wq, wq);
    tsplit_kernel<<<gt, 256>>>(Wo, wo);

    gemm3_mma<<<dim3(M_ / 64, N1 / 128), 256, 3 * ST3>>>();

    dim3 gscan(M_ / 128, NT, B_);
    carry_kernel<<<gscan, 128>>>(bg);
    prefix_kernel<<<(B_ * M_) / 256, 256>>>();
    apply_kernel<<<gscan, 128>>>(bg, bq);

    gemm_out_mma<<<dim3(E_ / 128, N1 / 128), 256, 3 * STO>>>(out);
}

// round 7
// speedup vs baseline: 5.1984x; 1.2888x over previous
#include <cuda_runtime.h>
#include <cuda_fp16.h>
#include <cstdint>
#include <math.h>

#define B_   4
#define S_   4096
#define E_   2048
#define M_   2048
#define N1   (B_ * S_)
#define DECAY_F 0.95f
#define SCALE_F 0.22360679774997896f
#define TS   256
#define NT   (S_ / TS)

// ---------------- device scratch ----------------
__device__ float g_v[(size_t)N1 * M_];     // raw x@Wv
__device__ float g_g[(size_t)N1 * M_];     // raw x@Wg
__device__ float g_q[(size_t)N1 * M_];     // raw x@Wq
__device__ float g_carry [B_ * NT * M_];
__device__ float g_prefix[B_ * NT * M_];
__device__ __half g_xh[(size_t)N1 * E_];
__device__ __half g_ldh[(size_t)N1 * M_];
__device__ __half g_wv[(size_t)E_ * M_];   // transposed [n][k] fp16
__device__ __half g_wg[(size_t)E_ * M_];
__device__ __half g_wq[(size_t)E_ * M_];
__device__ __half g_wo[(size_t)E_ * M_];

// ---------------- helpers ----------------
__device__ __forceinline__ uint32_t smem_u32(const void* p) {
    uint32_t a;
    asm("{ .reg .u64 t; cvta.to.shared.u64 t, %1; cvt.u32.u64 %0, t; }" : "=r"(a) : "l"(p));
    return a;
}
#define CP16(dst, src) \
    asm volatile("cp.async.cg.shared.global [%0], [%1], 16;" :: "r"(dst), "l"(src))
#define CP_COMMIT() asm volatile("cp.async.commit_group;" ::: "memory")
#define CP_WAIT(n)  asm volatile("cp.async.wait_group %0;" :: "n"(n) : "memory")

__device__ __forceinline__ void ldsm4(uint32_t* r, uint32_t addr) {
    asm volatile("ldmatrix.sync.aligned.m8n8.x4.shared.b16 {%0,%1,%2,%3}, [%4];"
        : "=r"(r[0]), "=r"(r[1]), "=r"(r[2]), "=r"(r[3]) : "r"(addr));
}
__device__ __forceinline__ void mma16816(float* d, const uint32_t* a, const uint32_t* b) {
    asm volatile(
        "mma.sync.aligned.m16n8k16.row.col.f32.f16.f16.f32 "
        "{%0,%1,%2,%3}, {%4,%5,%6,%7}, {%8,%9}, {%0,%1,%2,%3};"
        : "+f"(d[0]), "+f"(d[1]), "+f"(d[2]), "+f"(d[3])
        : "r"(a[0]), "r"(a[1]), "r"(a[2]), "r"(a[3]), "r"(b[0]), "r"(b[1]));
}
__device__ __forceinline__ float sigf(float v) { return 1.0f / (1.0f + __expf(-v)); }

#define PAD64 144   // 128B data + 16B pad: ldmatrix & cp.async conflict-free

// ---------------- conversion kernels ----------------
__global__ __launch_bounds__(256) void split_x_kernel(const float* __restrict__ x) {
    size_t i = (size_t)blockIdx.x * 256 + threadIdx.x;
    float4 v = reinterpret_cast<const float4*>(x)[i];
    reinterpret_cast<__half2*>(g_xh)[2*i] =
        __half2(__float2half(v.x), __float2half(v.y));
    reinterpret_cast<__half2*>(g_xh)[2*i+1] =
        __half2(__float2half(v.z), __float2half(v.w));
}

// W[k][n] -> T[n][k] fp16
__global__ __launch_bounds__(256) void tsplit_kernel(const float* __restrict__ W,
                                                     __half* __restrict__ Th) {
    __shared__ float tile[32][33];
    int bx = blockIdx.x * 32, by = blockIdx.y * 32;
    int tx = threadIdx.x & 31, ty = threadIdx.x >> 5;
    #pragma unroll
    for (int i = ty; i < 32; i += 8)
        tile[i][tx] = W[(size_t)(by + i) * M_ + bx + tx];
    __syncthreads();
    #pragma unroll
    for (int i = ty; i < 32; i += 8)
        Th[(size_t)(bx + i) * E_ + by + tx] = __float2half(tile[tx][i]);
}

// ---------------- gemm3: 128m x 192n (3 mats), warp 64m x 48n, BK=64 ----------------
#define ST3 ((128 + 192) * PAD64)       // 46080 B/stage
#define NKT3 (E_ / 64)                  // 32
__global__ __launch_bounds__(256, 1) void gemm3_mma() {
    extern __shared__ char sm[];
    uint32_t sb0 = smem_u32(sm);
    const int tid = threadIdx.x, wid = tid >> 5, lane = tid & 31;
    const int g = lane >> 2, t = lane & 3;
    const int wm = (wid & 1) * 64, wn = (wid >> 1) * 48;
    const int bn = blockIdx.x * 64, bm = blockIdx.y * 128;
    const int lrow = lane & 15;
    const int lcol = (lane >> 4) << 4;

    const __half* asrc = g_xh + (size_t)bm * E_;
    const __half* bsrc[3] = { g_wv + (size_t)bn * E_, g_wg + (size_t)bn * E_,
                              g_wq + (size_t)bn * E_ };

    float acc[4][6][4];
    #pragma unroll
    for (int i = 0; i < 4; i++)
        #pragma unroll
        for (int j = 0; j < 6; j++)
            #pragma unroll
            for (int e = 0; e < 4; e++) acc[i][j][e] = 0.f;

    auto load_stage = [&](int kt, int stg) {
        uint32_t sb = sb0 + stg * ST3;
        int k0 = kt * 64;
        #pragma unroll
        for (int j = 0; j < 10; j++) {                // 2560 CP16
            int idx = tid + j * 256;
            if (idx < 1024) {                         // A: 128 rows x 8 chunks
                int r = idx >> 3, c = idx & 7;
                CP16(sb + r * PAD64 + c * 16, asrc + (size_t)r * E_ + k0 + c * 8);
            } else {                                  // B: 192 rows x 8 chunks
                int rem = idx - 1024;
                int r = rem >> 3, c = rem & 7;
                int mat = r >> 6, nrow = r & 63;
                CP16(sb + (128 + r) * PAD64 + c * 16,
                     bsrc[mat] + (size_t)nrow * E_ + k0 + c * 8);
            }
        }
    };

    load_stage(0, 0); CP_COMMIT();
    load_stage(1, 1); CP_COMMIT();
    CP_WAIT(1);
    __syncthreads();

    for (int kt = 0; kt < NKT3; kt++) {
        int stg = kt % 3;
        uint32_t sA = sb0 + stg * ST3;
        uint32_t sB = sA + 128 * PAD64;
        uint32_t aRow = sA + (wm + lrow) * PAD64 + lcol;
        uint32_t bRow = sB + (wn + lrow) * PAD64 + lcol;

        if (kt + 2 < NKT3) load_stage(kt + 2, (kt + 2) % 3);
        CP_COMMIT();

        #pragma unroll
        for (int ks = 0; ks < 4; ks++) {
            int co = ks * 32;
            uint32_t a[4][4];
            #pragma unroll
            for (int mb = 0; mb < 4; mb++)
                ldsm4(a[mb], aRow + mb * (16 * PAD64) + co);
            #pragma unroll
            for (int p = 0; p < 3; p++) {             // nb pairs {0,1},{2,3},{4,5}
                uint32_t br[4];
                ldsm4(br, bRow + p * (16 * PAD64) + co);
                uint32_t b0[2] = { br[0], br[2] };
                uint32_t b1[2] = { br[1], br[3] };
                #pragma unroll
                for (int mb = 0; mb < 4; mb++) {
                    mma16816(acc[mb][2 * p],     a[mb], b0);
                    mma16816(acc[mb][2 * p + 1], a[mb], b1);
                }
            }
        }
        CP_WAIT(1);
        __syncthreads();
    }

    // raw outputs: route each 8-col block to its matrix's array
    #pragma unroll
    for (int mb = 0; mb < 4; mb++)
        #pragma unroll
        for (int nb = 0; nb < 6; nb++) {
            int c192 = wn + nb * 8 + 2 * t;           // col in [0,192)
            int mat = c192 >> 6;
            int mcol = bn + (c192 & 63);
            float* arr = (mat == 0) ? g_v : (mat == 1) ? g_g : g_q;
            #pragma unroll
            for (int h = 0; h < 2; h++) {
                size_t row = (size_t)(bm + wm + mb * 16 + g + h * 8);
                *reinterpret_cast<float2*>(&arr[row * M_ + mcol]) =
                    make_float2(acc[mb][nb][2 * h], acc[mb][nb][2 * h + 1]);
            }
        }
}

// ---------------- gemm_out: 128m x 128n, warp 64m x 32n, 1-pass, BK=64 ----------------
#define STO ((128 + 128) * PAD64)       // 36864 B/stage
#define NKTO (M_ / 64)                  // 32
__global__ __launch_bounds__(256, 1) void gemm_out_mma(float* __restrict__ out) {
    extern __shared__ char sm[];
    uint32_t sb0 = smem_u32(sm);
    const int tid = threadIdx.x, wid = tid >> 5, lane = tid & 31;
    const int g = lane >> 2, t = lane & 3;
    const int wm = (wid & 1) * 64, wn = (wid >> 1) * 32;
    const int bn = blockIdx.x * 128, bm = blockIdx.y * 128;
    const int lrow = lane & 15;
    const int lcol = (lane >> 4) << 4;

    const __half* asrc = g_ldh + (size_t)bm * M_;
    const __half* bsrc = g_wo + (size_t)bn * M_;

    float acc[4][4][4];
    #pragma unroll
    for (int i = 0; i < 4; i++)
        #pragma unroll
        for (int j = 0; j < 4; j++)
            #pragma unroll
            for (int e = 0; e < 4; e++) acc[i][j][e] = 0.f;

    auto load_stage = [&](int kt, int stg) {
        uint32_t sb = sb0 + stg * STO;
        int k0 = kt * 64;
        #pragma unroll
        for (int j = 0; j < 8; j++) {                 // 2048 CP16
            int idx = tid + j * 256;
            int half_ = idx >> 10, rem = idx & 1023, r = rem >> 3, c = rem & 7;
            const __half* src = half_ ? bsrc : asrc;
            CP16(sb + half_ * (128 * PAD64) + r * PAD64 + c * 16,
                 src + (size_t)r * M_ + k0 + c * 8);
        }
    };

    load_stage(0, 0); CP_COMMIT();
    load_stage(1, 1); CP_COMMIT();
    CP_WAIT(1);
    __syncthreads();

    for (int kt = 0; kt < NKTO; kt++) {
        int stg = kt % 3;
        uint32_t sb = sb0 + stg * STO;
        uint32_t aRow = sb + (wm + lrow) * PAD64 + lcol;
        uint32_t bRow = sb + 128 * PAD64 + (wn + lrow) * PAD64 + lcol;

        if (kt + 2 < NKTO) load_stage(kt + 2, (kt + 2) % 3);
        CP_COMMIT();

        #pragma unroll
        for (int ks = 0; ks < 4; ks++) {
            int co = ks * 32;
            uint32_t a[4][4];
            #pragma unroll
            for (int mb = 0; mb < 4; mb++)
                ldsm4(a[mb], aRow + mb * (16 * PAD64) + co);
            #pragma unroll
            for (int p = 0; p < 2; p++) {             // nb pairs {0,1},{2,3}
                uint32_t br[4];
                ldsm4(br, bRow + p * (16 * PAD64) + co);
                uint32_t b0[2] = { br[0], br[2] };
                uint32_t b1[2] = { br[1], br[3] };
                #pragma unroll
                for (int mb = 0; mb < 4; mb++) {
                    mma16816(acc[mb][2 * p],     a[mb], b0);
                    mma16816(acc[mb][2 * p + 1], a[mb], b1);
                }
            }
        }
        CP_WAIT(1);
        __syncthreads();
    }

    #pragma unroll
    for (int mb = 0; mb < 4; mb++)
        #pragma unroll
        for (int nb = 0; nb < 4; nb++) {
            int col = bn + wn + nb * 8 + 2 * t;
            #pragma unroll
            for (int h = 0; h < 2; h++) {
                size_t row = (size_t)(bm + wm + mb * 16 + g + h * 8);
                *reinterpret_cast<float2*>(&out[row * E_ + col]) =
                    make_float2(acc[mb][nb][2 * h], acc[mb][nb][2 * h + 1]);
            }
        }
}

// ---------------- scan kernels (gating fused) ----------------
__global__ __launch_bounds__(128) void carry_kernel(const float* __restrict__ bg) {
    int m = blockIdx.x * 128 + threadIdx.x;
    int j = blockIdx.y, b = blockIdx.z;
    size_t base = ((size_t)(b * S_ + j * TS)) * M_ + m;
    float bgm = bg[m];
    float c = 0.f;
    #pragma unroll 4
    for (int t = 0; t < TS; t++) {
        size_t idx = base + (size_t)t * M_;
        float s = g_v[idx] * sigf(g_g[idx] + bgm) * SCALE_F;
        c = fmaf(DECAY_F, c, s);
    }
    g_carry[(size_t)(b * NT + j) * M_ + m] = c;
}

__global__ __launch_bounds__(256) void prefix_kernel() {
    int gid = blockIdx.x * blockDim.x + threadIdx.x;
    int b = gid / M_, m = gid % M_;
    float aTS = DECAY_F;
    #pragma unroll
    for (int i = 0; i < 8; i++) aTS *= aTS;          // 0.95^256
    float run = 0.f;
    #pragma unroll
    for (int j = 0; j < NT; j++) {
        size_t idx = (size_t)(b * NT + j) * M_ + m;
        g_prefix[idx] = run;
        run = g_carry[idx] + aTS * run;
    }
}

__global__ __launch_bounds__(128) void apply_kernel(const float* __restrict__ bg,
                                                    const float* __restrict__ bq) {
    int m = blockIdx.x * 128 + threadIdx.x;
    int j = blockIdx.y, b = blockIdx.z;
    size_t base = ((size_t)(b * S_ + j * TS)) * M_ + m;
    float bgm = bg[m], bqm = bq[m];
    float c = g_prefix[(size_t)(b * NT + j) * M_ + m];
    #pragma unroll 4
    for (int t = 0; t < TS; t++) {
        size_t idx = base + (size_t)t * M_;
        float s = g_v[idx] * sigf(g_g[idx] + bgm) * SCALE_F;
        c = fmaf(DECAY_F, c, s);
        float que = sigf(g_q[idx] + bqm) * SCALE_F;
        g_ldh[idx] = __float2half(c * que);
    }
}

// ---------------- launch ----------------
extern "C" void kernel_launch(void* const* d_in, const int* in_sizes, int n_in,
                              void* d_out, int out_size) {
    const float* x  = (const float*)d_in[0];
    const float* Wv = (const float*)d_in[1];
    const float* Wg = (const float*)d_in[2];
    const float* bg = (const float*)d_in[3];
    const float* Wq = (const float*)d_in[4];
    const float* bq = (const float*)d_in[5];
    const float* Wo = (const float*)d_in[6];
    float* out = (float*)d_out;

    cudaFuncSetAttribute(gemm3_mma, cudaFuncAttributeMaxDynamicSharedMemorySize, 3 * ST3);
    cudaFuncSetAttribute(gemm_out_mma, cudaFuncAttributeMaxDynamicSharedMemorySize, 3 * STO);

    __half *wv, *wg, *wq, *wo;
    cudaGetSymbolAddress((void**)&wv, g_wv);
    cudaGetSymbolAddress((void**)&wg, g_wg);
    cudaGetSymbolAddress((void**)&wq, g_wq);
    cudaGetSymbolAddress((void**)&wo, g_wo);

    split_x_kernel<<<((size_t)N1 * E_ / 4) / 256, 256>>>(x);
    dim3 gt(M_ / 32, E_ / 32);
    tsplit_kernel<<<gt, 256>>>(Wv, wv);
    tsplit_kernel<<<gt, 256>>>(Wg, wg);
    tsplit_kernel<<<gt, 256>>>(Wq, wq);
    tsplit_kernel<<<gt, 256>>>(Wo, wo);

    gemm3_mma<<<dim3(M_ / 64, N1 / 128), 256, 3 * ST3>>>();

    dim3 gscan(M_ / 128, NT, B_);
    carry_kernel<<<gscan, 128>>>(bg);
    prefix_kernel<<<(B_ * M_) / 256, 256>>>();
    apply_kernel<<<gscan, 128>>>(bg, bq);

    gemm_out_mma<<<dim3(E_ / 128, N1 / 128), 256, 3 * STO>>>(out);
}

// round 8
// speedup vs baseline: 5.4367x; 1.0458x over previous
#include <cuda_runtime.h>
#include <cuda_fp16.h>
#include <cstdint>
#include <math.h>

#define B_   4
#define S_   4096
#define E_   2048
#define M_   2048
#define N1   (B_ * S_)
#define DECAY_F 0.95f
#define SCALE_F 0.22360679774997896f
#define TS   256
#define NT   (S_ / TS)

// ---------------- device scratch ----------------
__device__ float g_store[(size_t)N1 * M_];   // v * sigmoid(g+bg) * scale
__device__ float g_que  [(size_t)N1 * M_];   // sigmoid(q+bq) * scale
__device__ float g_carry [B_ * NT * M_];
__device__ float g_prefix[B_ * NT * M_];
__device__ __half g_xh[(size_t)N1 * E_];
__device__ __half g_ldh[(size_t)N1 * M_];
__device__ __half g_wv[(size_t)E_ * M_];   // transposed [n][k] fp16
__device__ __half g_wg[(size_t)E_ * M_];
__device__ __half g_wq[(size_t)E_ * M_];
__device__ __half g_wo[(size_t)E_ * M_];

// ---------------- helpers ----------------
__device__ __forceinline__ uint32_t smem_u32(const void* p) {
    uint32_t a;
    asm("{ .reg .u64 t; cvta.to.shared.u64 t, %1; cvt.u32.u64 %0, t; }" : "=r"(a) : "l"(p));
    return a;
}
#define CP16(dst, src) \
    asm volatile("cp.async.cg.shared.global [%0], [%1], 16;" :: "r"(dst), "l"(src))
#define CP_COMMIT() asm volatile("cp.async.commit_group;" ::: "memory")
#define CP_WAIT(n)  asm volatile("cp.async.wait_group %0;" :: "n"(n) : "memory")

__device__ __forceinline__ void ldsm4(uint32_t* r, uint32_t addr) {
    asm volatile("ldmatrix.sync.aligned.m8n8.x4.shared.b16 {%0,%1,%2,%3}, [%4];"
        : "=r"(r[0]), "=r"(r[1]), "=r"(r[2]), "=r"(r[3]) : "r"(addr));
}
__device__ __forceinline__ void mma16816(float* d, const uint32_t* a, const uint32_t* b) {
    asm volatile(
        "mma.sync.aligned.m16n8k16.row.col.f32.f16.f16.f32 "
        "{%0,%1,%2,%3}, {%4,%5,%6,%7}, {%8,%9}, {%0,%1,%2,%3};"
        : "+f"(d[0]), "+f"(d[1]), "+f"(d[2]), "+f"(d[3])
        : "r"(a[0]), "r"(a[1]), "r"(a[2]), "r"(a[3]), "r"(b[0]), "r"(b[1]));
}
__device__ __forceinline__ float sigf(float v) { return 1.0f / (1.0f + __expf(-v)); }

#define PAD64 144   // 128B data + 16B pad: ldmatrix & cp.async conflict-free

// ---------------- conversion kernels ----------------
__global__ __launch_bounds__(256) void split_x_kernel(const float* __restrict__ x) {
    size_t i = (size_t)blockIdx.x * 256 + threadIdx.x;
    float4 v = reinterpret_cast<const float4*>(x)[i];
    reinterpret_cast<__half2*>(g_xh)[2*i] =
        __half2(__float2half(v.x), __float2half(v.y));
    reinterpret_cast<__half2*>(g_xh)[2*i+1] =
        __half2(__float2half(v.z), __float2half(v.w));
}

// W[k][n] -> T[n][k] fp16
__global__ __launch_bounds__(256) void tsplit_kernel(const float* __restrict__ W,
                                                     __half* __restrict__ Th) {
    __shared__ float tile[32][33];
    int bx = blockIdx.x * 32, by = blockIdx.y * 32;
    int tx = threadIdx.x & 31, ty = threadIdx.x >> 5;
    #pragma unroll
    for (int i = ty; i < 32; i += 8)
        tile[i][tx] = W[(size_t)(by + i) * M_ + bx + tx];
    __syncthreads();
    #pragma unroll
    for (int i = ty; i < 32; i += 8)
        Th[(size_t)(bx + i) * E_ + by + tx] = __float2half(tile[tx][i]);
}

// ---------------- gemm3: 128m x 192n (3 mats), warp 64m x 48n, BK=64 ----------------
#define ST3 ((128 + 192) * PAD64)       // 46080 B/stage
#define NKT3 (E_ / 64)                  // 32
#define FST 194                          // fp32 epilogue tile row stride (floats)
#define SM3 (3 * ST3)                    // 138240 B >= 128*194*4 = 99328 B
__global__ __launch_bounds__(256, 1) void gemm3_mma(const float* __restrict__ bg,
                                                    const float* __restrict__ bq) {
    extern __shared__ char sm[];
    uint32_t sb0 = smem_u32(sm);
    const int tid = threadIdx.x, wid = tid >> 5, lane = tid & 31;
    const int g = lane >> 2, t = lane & 3;
    const int wm = (wid & 1) * 64, wn = (wid >> 1) * 48;
    const int bn = blockIdx.x * 64, bm = blockIdx.y * 128;
    const int lrow = lane & 15;
    const int lcol = (lane >> 4) << 4;

    const __half* asrc = g_xh + (size_t)bm * E_;
    const __half* bsrc[3] = { g_wv + (size_t)bn * E_, g_wg + (size_t)bn * E_,
                              g_wq + (size_t)bn * E_ };

    float acc[4][6][4];
    #pragma unroll
    for (int i = 0; i < 4; i++)
        #pragma unroll
        for (int j = 0; j < 6; j++)
            #pragma unroll
            for (int e = 0; e < 4; e++) acc[i][j][e] = 0.f;

    auto load_stage = [&](int kt, int stg) {
        uint32_t sb = sb0 + stg * ST3;
        int k0 = kt * 64;
        #pragma unroll
        for (int j = 0; j < 10; j++) {                // 2560 CP16
            int idx = tid + j * 256;
            if (idx < 1024) {                         // A: 128 rows x 8 chunks
                int r = idx >> 3, c = idx & 7;
                CP16(sb + r * PAD64 + c * 16, asrc + (size_t)r * E_ + k0 + c * 8);
            } else {                                  // B: 192 rows x 8 chunks
                int rem = idx - 1024;
                int r = rem >> 3, c = rem & 7;
                int mat = r >> 6, nrow = r & 63;
                CP16(sb + (128 + r) * PAD64 + c * 16,
                     bsrc[mat] + (size_t)nrow * E_ + k0 + c * 8);
            }
        }
    };

    load_stage(0, 0); CP_COMMIT();
    load_stage(1, 1); CP_COMMIT();
    CP_WAIT(1);
    __syncthreads();

    for (int kt = 0; kt < NKT3; kt++) {
        int stg = kt % 3;
        uint32_t sA = sb0 + stg * ST3;
        uint32_t sB = sA + 128 * PAD64;
        uint32_t aRow = sA + (wm + lrow) * PAD64 + lcol;
        uint32_t bRow = sB + (wn + lrow) * PAD64 + lcol;

        if (kt + 2 < NKT3) load_stage(kt + 2, (kt + 2) % 3);
        CP_COMMIT();

        #pragma unroll
        for (int ks = 0; ks < 4; ks++) {
            int co = ks * 32;
            uint32_t a[4][4];
            #pragma unroll
            for (int mb = 0; mb < 4; mb++)
                ldsm4(a[mb], aRow + mb * (16 * PAD64) + co);
            #pragma unroll
            for (int p = 0; p < 3; p++) {             // nb pairs {0,1},{2,3},{4,5}
                uint32_t br[4];
                ldsm4(br, bRow + p * (16 * PAD64) + co);
                uint32_t b0[2] = { br[0], br[2] };
                uint32_t b1[2] = { br[1], br[3] };
                #pragma unroll
                for (int mb = 0; mb < 4; mb++) {
                    mma16816(acc[mb][2 * p],     a[mb], b0);
                    mma16816(acc[mb][2 * p + 1], a[mb], b1);
                }
            }
        }
        CP_WAIT(1);
        __syncthreads();
    }

    // ---- fused epilogue: stage fp32 tile in smem, re-partition, gate ----
    float* sf = reinterpret_cast<float*>(sm);
    #pragma unroll
    for (int mb = 0; mb < 4; mb++)
        #pragma unroll
        for (int nb = 0; nb < 6; nb++) {
            int c192 = wn + nb * 8 + 2 * t;
            #pragma unroll
            for (int h = 0; h < 2; h++) {
                int r = wm + mb * 16 + g + h * 8;
                *reinterpret_cast<float2*>(&sf[r * FST + c192]) =
                    make_float2(acc[mb][nb][2 * h], acc[mb][nb][2 * h + 1]);
            }
        }
    __syncthreads();

    {
        int c = tid & 63;
        int m = bn + c;
        float bgm = bg[m], bqm = bq[m];
        int r0 = tid >> 6;                            // 0..3
        #pragma unroll 8
        for (int i = 0; i < 32; i++) {
            int r = r0 + i * 4;
            float v  = sf[r * FST + c];
            float gg = sf[r * FST + 64 + c];
            float qq = sf[r * FST + 128 + c];
            size_t row = (size_t)(bm + r);
            g_store[row * M_ + m] = v * sigf(gg + bgm) * SCALE_F;
            g_que[row * M_ + m]   = sigf(qq + bqm) * SCALE_F;
        }
    }
}

// ---------------- gemm_out: 128m x 128n, warp 64m x 32n, 1-pass, BK=64, 2 CTA/SM ----------------
#define STO ((128 + 128) * PAD64)       // 36864 B/stage
#define NKTO (M_ / 64)                  // 32
__global__ __launch_bounds__(256, 2) void gemm_out_mma(float* __restrict__ out) {
    extern __shared__ char sm[];
    uint32_t sb0 = smem_u32(sm);
    const int tid = threadIdx.x, wid = tid >> 5, lane = tid & 31;
    const int g = lane >> 2, t = lane & 3;
    const int wm = (wid & 1) * 64, wn = (wid >> 1) * 32;
    const int bn = blockIdx.x * 128, bm = blockIdx.y * 128;
    const int lrow = lane & 15;
    const int lcol = (lane >> 4) << 4;

    const __half* asrc = g_ldh + (size_t)bm * M_;
    const __half* bsrc = g_wo + (size_t)bn * M_;

    float acc[4][4][4];
    #pragma unroll
    for (int i = 0; i < 4; i++)
        #pragma unroll
        for (int j = 0; j < 4; j++)
            #pragma unroll
            for (int e = 0; e < 4; e++) acc[i][j][e] = 0.f;

    auto load_stage = [&](int kt, int stg) {
        uint32_t sb = sb0 + stg * STO;
        int k0 = kt * 64;
        #pragma unroll
        for (int j = 0; j < 8; j++) {                 // 2048 CP16
            int idx = tid + j * 256;
            int half_ = idx >> 10, rem = idx & 1023, r = rem >> 3, c = rem & 7;
            const __half* src = half_ ? bsrc : asrc;
            CP16(sb + half_ * (128 * PAD64) + r * PAD64 + c * 16,
                 src + (size_t)r * M_ + k0 + c * 8);
        }
    };

    load_stage(0, 0); CP_COMMIT();

    for (int kt = 0; kt < NKTO; kt++) {
        if (kt + 1 < NKTO) {
            load_stage(kt + 1, (kt + 1) & 1);
            CP_COMMIT();
            CP_WAIT(1);
        } else {
            CP_WAIT(0);
        }
        __syncthreads();

        uint32_t sb = sb0 + (kt & 1) * STO;
        uint32_t aRow = sb + (wm + lrow) * PAD64 + lcol;
        uint32_t bRow = sb + 128 * PAD64 + (wn + lrow) * PAD64 + lcol;
        #pragma unroll
        for (int ks = 0; ks < 4; ks++) {
            int co = ks * 32;
            uint32_t a[4][4];
            #pragma unroll
            for (int mb = 0; mb < 4; mb++)
                ldsm4(a[mb], aRow + mb * (16 * PAD64) + co);
            #pragma unroll
            for (int p = 0; p < 2; p++) {
                uint32_t br[4];
                ldsm4(br, bRow + p * (16 * PAD64) + co);
                uint32_t b0[2] = { br[0], br[2] };
                uint32_t b1[2] = { br[1], br[3] };
                #pragma unroll
                for (int mb = 0; mb < 4; mb++) {
                    mma16816(acc[mb][2 * p],     a[mb], b0);
                    mma16816(acc[mb][2 * p + 1], a[mb], b1);
                }
            }
        }
        __syncthreads();
    }

    #pragma unroll
    for (int mb = 0; mb < 4; mb++)
        #pragma unroll
        for (int nb = 0; nb < 4; nb++) {
            int col = bn + wn + nb * 8 + 2 * t;
            #pragma unroll
            for (int h = 0; h < 2; h++) {
                size_t row = (size_t)(bm + wm + mb * 16 + g + h * 8);
                *reinterpret_cast<float2*>(&out[row * E_ + col]) =
                    make_float2(acc[mb][nb][2 * h], acc[mb][nb][2 * h + 1]);
            }
        }
}

// ---------------- scan kernels ----------------
__global__ __launch_bounds__(128) void carry_kernel() {
    int m = blockIdx.x * 128 + threadIdx.x;
    int j = blockIdx.y, b = blockIdx.z;
    size_t base = ((size_t)(b * S_ + j * TS)) * M_ + m;
    float c = 0.f;
    #pragma unroll 8
    for (int t = 0; t < TS; t++)
        c = fmaf(DECAY_F, c, g_store[base + (size_t)t * M_]);
    g_carry[(size_t)(b * NT + j) * M_ + m] = c;
}

__global__ __launch_bounds__(256) void prefix_kernel() {
    int gid = blockIdx.x * blockDim.x + threadIdx.x;
    int b = gid / M_, m = gid % M_;
    float aTS = DECAY_F;
    #pragma unroll
    for (int i = 0; i < 8; i++) aTS *= aTS;          // 0.95^256
    float run = 0.f;
    #pragma unroll
    for (int j = 0; j < NT; j++) {
        size_t idx = (size_t)(b * NT + j) * M_ + m;
        g_prefix[idx] = run;
        run = g_carry[idx] + aTS * run;
    }
}

__global__ __launch_bounds__(128) void apply_kernel() {
    int m = blockIdx.x * 128 + threadIdx.x;
    int j = blockIdx.y, b = blockIdx.z;
    size_t base = ((size_t)(b * S_ + j * TS)) * M_ + m;
    float c = g_prefix[(size_t)(b * NT + j) * M_ + m];
    #pragma unroll 4
    for (int t = 0; t < TS; t++) {
        size_t idx = base + (size_t)t * M_;
        c = fmaf(DECAY_F, c, g_store[idx]);
        g_ldh[idx] = __float2half(c * g_que[idx]);
    }
}

// ---------------- launch ----------------
extern "C" void kernel_launch(void* const* d_in, const int* in_sizes, int n_in,
                              void* d_out, int out_size) {
    const float* x  = (const float*)d_in[0];
    const float* Wv = (const float*)d_in[1];
    const float* Wg = (const float*)d_in[2];
    const float* bg = (const float*)d_in[3];
    const float* Wq = (const float*)d_in[4];
    const float* bq = (const float*)d_in[5];
    const float* Wo = (const float*)d_in[6];
    float* out = (float*)d_out;

    cudaFuncSetAttribute(gemm3_mma, cudaFuncAttributeMaxDynamicSharedMemorySize, SM3);
    cudaFuncSetAttribute(gemm_out_mma, cudaFuncAttributeMaxDynamicSharedMemorySize, 2 * STO);

    __half *wv, *wg, *wq, *wo;
    cudaGetSymbolAddress((void**)&wv, g_wv);
    cudaGetSymbolAddress((void**)&wg, g_wg);
    cudaGetSymbolAddress((void**)&wq, g_wq);
    cudaGetSymbolAddress((void**)&wo, g_wo);

    split_x_kernel<<<((size_t)N1 * E_ / 4) / 256, 256>>>(x);
    dim3 gt(M_ / 32, E_ / 32);
    tsplit_kernel<<<gt, 256>>>(Wv, wv);
    tsplit_kernel<<<gt, 256>>>(Wg, wg);
    tsplit_kernel<<<gt, 256>>>(Wq, wq);
    tsplit_kernel<<<gt, 256>>>(Wo, wo);

    gemm3_mma<<<dim3(M_ / 64, N1 / 128), 256, SM3>>>(bg, bq);

    dim3 gscan(M_ / 128, NT, B_);
    carry_kernel<<<gscan, 128>>>();
    prefix_kernel<<<(B_ * M_) / 256, 256>>>();
    apply_kernel<<<gscan, 128>>>();

    gemm_out_mma<<<dim3(E_ / 128, N1 / 128), 256, 2 * STO>>>(out);
}